// round 15
// baseline (speedup 1.0000x reference)
#include <cuda_runtime.h>
#include <cuda_bf16.h>
#include <math.h>
#include <stdint.h>

// ---- problem dims ----
#define Bb   16
#define Ll   512
#define Mm   32
#define PREDp 96
#define Pp   16
#define Sss  8
#define Dd   128
#define NSTn 16
#define DCc  4
#define NLl  4
#define Nn   63
#define DIi  256
#define DTRr 8
#define BMr  512
#define TT   32256        // = 512*63 = 1008*32 = 252*128
#define BNb  1008
#define KSPLIT 21         // head GEMM split-K slices (8064 = 21*384)

// ---- static device scratch ----
__device__ float g_y[9][(size_t)TT * Dd];
__device__ float g_xn[(size_t)BMr * Ll];
__device__ float g_mean[BMr];
__device__ float g_std[BMr];
__device__ float g_tokin[(size_t)TT * Dd];
__device__ float g_xz[(size_t)TT * 1024];      // up to 2 roles x (xi|z)
__device__ float g_u[(size_t)TT * 512];        // conv+silu output, up to 2 roles
__device__ float g_xdbl[(size_t)TT * 80];      // x_proj output, up to 2 roles x 40
__device__ float g_ys[(size_t)TT * 512];       // scan output, up to 2 roles
__device__ float g_norm[(size_t)TT * Dd];
__device__ float g_chr[(size_t)TT * Dd];
__device__ float g_wpack[4 * 128 * 512];
__device__ float g_headp[(size_t)KSPLIT * BMr * PREDp];

// ======================= warp-mma bf16-split GEMM =======================
// C[M,NT] = A[M,K] @ Bw[NT,K]^T, fp32 in/out, bf16 hi/lo split (3 HMMA terms).
// A row stride = lda (>= K), B row stride = K.
// grid = (ceil(NT/64), M/128, nz), block = 256 (8 warps of 32x32 tiles).
// flags: 1 = accumulate into C, 2 = add R, 4 = transposed epilogue,
//        8 = dual-role mode (blockIdx.z selects role: A+=z*256, B+=z*40*K, C+=z*TT*40).

#define SASTR 40   // smem row stride (bf16): 80B -> conflict-free ldmatrix

__device__ __forceinline__ uint32_t smem_u32(const void* p) {
    return (uint32_t)__cvta_generic_to_shared(p);
}

__device__ __forceinline__ void mma16816(float* d, const uint32_t* a, const uint32_t* b) {
    asm volatile(
        "mma.sync.aligned.m16n8k16.row.col.f32.bf16.bf16.f32 "
        "{%0,%1,%2,%3},{%4,%5,%6,%7},{%8,%9},{%0,%1,%2,%3};"
        : "+f"(d[0]), "+f"(d[1]), "+f"(d[2]), "+f"(d[3])
        : "r"(a[0]), "r"(a[1]), "r"(a[2]), "r"(a[3]), "r"(b[0]), "r"(b[1]));
}

__device__ __forceinline__ void ldm_x4(uint32_t* r, uint32_t a) {
    asm volatile("ldmatrix.sync.aligned.m8n8.x4.shared.b16 {%0,%1,%2,%3}, [%4];"
                 : "=r"(r[0]), "=r"(r[1]), "=r"(r[2]), "=r"(r[3]) : "r"(a));
}

union BH2 { __nv_bfloat16 h[2]; uint32_t u; };

__device__ __forceinline__ int trow(int row) {
    int m = row & 31;
    int bn = row >> 5;
    int n = bn % Nn, b = bn / Nn;
    return (b * Mm + m) * Nn + n;
}

template <int NT>
__global__ __launch_bounds__(256) void k_mma(const float* __restrict__ A,
                                             const float* __restrict__ Bw,
                                             float* __restrict__ C,
                                             const float* __restrict__ R,
                                             int K, int lda, int klen, int flags) {
    __shared__ __nv_bfloat16 sA[2][128 * SASTR];
    __shared__ __nv_bfloat16 sB[2][64 * SASTR];

    int tid = threadIdx.x;
    int warp = tid >> 5, lane = tid & 31;
    int gq = lane >> 2, tig = lane & 3;
    int warpM = warp >> 1, warpN = warp & 1;
    int m0 = blockIdx.y * 128;
    int n0 = blockIdx.x * 64;
    int kbeg;
    if (flags & 8) {
        A  += (size_t)blockIdx.z * 256;
        Bw += (size_t)blockIdx.z * 40 * K;
        C  += (size_t)blockIdx.z * ((size_t)TT * 40);
        kbeg = 0;
    } else {
        kbeg = blockIdx.z * klen;
        C += (size_t)blockIdx.z * ((size_t)gridDim.y * 128) * NT;
    }

    int g = lane >> 3, rr = lane & 7;
    int aoff = (warpM * 32 + (g & 1) * 8 + rr) * SASTR + (g >> 1) * 8;
    int boff = (warpN * 32 + (g >> 1) * 8 + rr) * SASTR + (g & 1) * 8;
    uint32_t sA0 = smem_u32(&sA[0][0]), sA1 = smem_u32(&sA[1][0]);
    uint32_t sB0 = smem_u32(&sB[0][0]), sB1 = smem_u32(&sB[1][0]);

    float acc[2][4][4];
#pragma unroll
    for (int i = 0; i < 2; ++i)
#pragma unroll
        for (int j = 0; j < 4; ++j)
#pragma unroll
            for (int r = 0; r < 4; ++r) acc[i][j][r] = 0.f;

    float4 ra[4], rb[2];

    auto ldA = [&](int k0) {
#pragma unroll
        for (int t = 0; t < 4; ++t) {
            int gg = tid + t * 256;
            int row = gg >> 3, c = (gg & 7) << 2;
            ra[t] = *reinterpret_cast<const float4*>(A + (size_t)(m0 + row) * lda + k0 + c);
        }
    };
    auto ldB = [&](int k0) {
#pragma unroll
        for (int t = 0; t < 2; ++t) {
            int gg = tid + t * 256;
            int row = gg >> 3, c = (gg & 7) << 2;
            int grow = n0 + row;
            if ((NT & 63) == 0 || grow < NT)
                rb[t] = *reinterpret_cast<const float4*>(Bw + (size_t)grow * K + k0 + c);
            else
                rb[t] = make_float4(0.f, 0.f, 0.f, 0.f);
        }
    };

    ldA(kbeg); ldB(kbeg);
    int nch = klen >> 5;
    for (int ch = 0; ch < nch; ++ch) {
#pragma unroll
        for (int t = 0; t < 4; ++t) {
            int gg = tid + t * 256;
            int row = gg >> 3, c = (gg & 7) << 2;
            float v[4] = {ra[t].x, ra[t].y, ra[t].z, ra[t].w};
            BH2 h0, h1, l0, l1;
#pragma unroll
            for (int q = 0; q < 2; ++q) {
                h0.h[q] = __float2bfloat16(v[q]);
                l0.h[q] = __float2bfloat16(v[q] - __bfloat162float(h0.h[q]));
                h1.h[q] = __float2bfloat16(v[2 + q]);
                l1.h[q] = __float2bfloat16(v[2 + q] - __bfloat162float(h1.h[q]));
            }
            uint32_t* ph = reinterpret_cast<uint32_t*>(&sA[0][row * SASTR + c]);
            uint32_t* pl = reinterpret_cast<uint32_t*>(&sA[1][row * SASTR + c]);
            ph[0] = h0.u; ph[1] = h1.u; pl[0] = l0.u; pl[1] = l1.u;
        }
#pragma unroll
        for (int t = 0; t < 2; ++t) {
            int gg = tid + t * 256;
            int row = gg >> 3, c = (gg & 7) << 2;
            float v[4] = {rb[t].x, rb[t].y, rb[t].z, rb[t].w};
            BH2 h0, h1, l0, l1;
#pragma unroll
            for (int q = 0; q < 2; ++q) {
                h0.h[q] = __float2bfloat16(v[q]);
                l0.h[q] = __float2bfloat16(v[q] - __bfloat162float(h0.h[q]));
                h1.h[q] = __float2bfloat16(v[2 + q]);
                l1.h[q] = __float2bfloat16(v[2 + q] - __bfloat162float(h1.h[q]));
            }
            uint32_t* ph = reinterpret_cast<uint32_t*>(&sB[0][row * SASTR + c]);
            uint32_t* pl = reinterpret_cast<uint32_t*>(&sB[1][row * SASTR + c]);
            ph[0] = h0.u; ph[1] = h1.u; pl[0] = l0.u; pl[1] = l1.u;
        }
        __syncthreads();
        if (ch + 1 < nch) { ldA(kbeg + ((ch + 1) << 5)); ldB(kbeg + ((ch + 1) << 5)); }

#pragma unroll
        for (int kk = 0; kk < 2; ++kk) {
            int kb = kk * 16;
            uint32_t ah[2][4], al[2][4];
            ldm_x4(ah[0], sA0 + (uint32_t)(aoff + kb) * 2);
            ldm_x4(ah[1], sA0 + (uint32_t)(aoff + 16 * SASTR + kb) * 2);
            ldm_x4(al[0], sA1 + (uint32_t)(aoff + kb) * 2);
            ldm_x4(al[1], sA1 + (uint32_t)(aoff + 16 * SASTR + kb) * 2);
            uint32_t bh[4][2], bl[4][2], t0[4], t1[4];
            ldm_x4(t0, sB0 + (uint32_t)(boff + kb) * 2);
            ldm_x4(t1, sB0 + (uint32_t)(boff + 16 * SASTR + kb) * 2);
            bh[0][0] = t0[0]; bh[0][1] = t0[1]; bh[1][0] = t0[2]; bh[1][1] = t0[3];
            bh[2][0] = t1[0]; bh[2][1] = t1[1]; bh[3][0] = t1[2]; bh[3][1] = t1[3];
            ldm_x4(t0, sB1 + (uint32_t)(boff + kb) * 2);
            ldm_x4(t1, sB1 + (uint32_t)(boff + 16 * SASTR + kb) * 2);
            bl[0][0] = t0[0]; bl[0][1] = t0[1]; bl[1][0] = t0[2]; bl[1][1] = t0[3];
            bl[2][0] = t1[0]; bl[2][1] = t1[1]; bl[3][0] = t1[2]; bl[3][1] = t1[3];
#pragma unroll
            for (int i = 0; i < 2; ++i)
#pragma unroll
                for (int j = 0; j < 4; ++j) {
                    mma16816(acc[i][j], ah[i], bh[j]);
                    mma16816(acc[i][j], ah[i], bl[j]);
                    mma16816(acc[i][j], al[i], bh[j]);
                }
        }
        __syncthreads();
    }

#pragma unroll
    for (int i = 0; i < 2; ++i) {
        int grow = m0 + warpM * 32 + i * 16 + gq;
        int orow0 = (flags & 4) ? trow(grow) : grow;
        int orow1 = (flags & 4) ? trow(grow + 8) : (grow + 8);
#pragma unroll
        for (int j = 0; j < 4; ++j) {
            int gcol = n0 + warpN * 32 + j * 8 + 2 * tig;
            if ((NT & 63) != 0 && gcol >= NT) continue;
            size_t o0 = (size_t)orow0 * NT + gcol;
            size_t o1 = (size_t)orow1 * NT + gcol;
            float2 v0 = make_float2(acc[i][j][0], acc[i][j][1]);
            float2 v1 = make_float2(acc[i][j][2], acc[i][j][3]);
            if (flags & 2) {
                float2 t0 = *reinterpret_cast<const float2*>(R + o0);
                float2 t1 = *reinterpret_cast<const float2*>(R + o1);
                v0.x += t0.x; v0.y += t0.y; v1.x += t1.x; v1.y += t1.y;
            }
            if (flags & 1) {
                float2 t0 = *reinterpret_cast<const float2*>(C + o0);
                float2 t1 = *reinterpret_cast<const float2*>(C + o1);
                v0.x += t0.x; v0.y += t0.y; v1.x += t1.x; v1.y += t1.y;
            }
            *reinterpret_cast<float2*>(C + o0) = v0;
            *reinterpret_cast<float2*>(C + o1) = v1;
        }
    }
}

// ======================= conv + SiLU (elementwise, multi-role) =======================
__global__ void k_conv(const float* __restrict__ xz, int xzs,
                       const float* __restrict__ cw, const float* __restrict__ cb,
                       float* __restrict__ u, int ustr, int batch, int slen) {
    int r = blockIdx.y;
    int rev = r;
    xz += (size_t)r * 512;
    cw += (size_t)r * DIi * DCc;
    cb += (size_t)r * DIi;
    u  += (size_t)r * 256;
    int idx = blockIdx.x * 256 + threadIdx.x;
    int total = batch * slen * DIi;
    if (idx >= total) return;
    int c = idx & 255;
    int row = idx >> 8;
    int s = row % slen, b = row / slen;
    float acc = cb[c];
#pragma unroll
    for (int k = 0; k < DCc; ++k) {
        int t = rev ? (s + 3 - k) : (s + k - 3);
        if (t >= 0 && t < slen)
            acc = fmaf(cw[c * DCc + k], xz[((size_t)(b * slen + t)) * xzs + c], acc);
    }
    u[(size_t)row * ustr + c] = acc / (1.f + __expf(-acc));
}

// ======================= scan (no matvec, one sync/step, multi-role) =======================
__global__ __launch_bounds__(256) void k_scan(
    const float* __restrict__ xz, int xzs,
    const float* __restrict__ xdbl, size_t xdstr,
    const float* __restrict__ u, int ustr,
    const float* __restrict__ dtw, const float* __restrict__ dtb,
    const float* __restrict__ alog, const float* __restrict__ dssm,
    float* __restrict__ y, int ystr, int slen) {
    __shared__ float sxd[2][40];

    int r = blockIdx.y;
    int rev = r;
    xz   += (size_t)r * 512;
    xdbl += (size_t)r * xdstr;
    u    += (size_t)r * 256;
    dtw  += (size_t)r * DIi * DTRr;
    dtb  += (size_t)r * DIi;
    alog += (size_t)r * DIi * NSTn;
    dssm += (size_t)r * DIi;
    y    += (size_t)r * 256;

    int c = threadIdx.x;
    int b = blockIdx.x;

    float dtwr[DTRr];
#pragma unroll
    for (int q = 0; q < DTRr; ++q) dtwr[q] = dtw[c * DTRr + q];
    float dtbr = dtb[c];
    float dss = dssm[c];

    float a[NSTn];
#pragma unroll
    for (int n = 0; n < NSTn; ++n) a[n] = -__expf(alog[c * NSTn + n]);
    float a0 = a[0];
    bool geom = true;
#pragma unroll
    for (int n = 1; n < NSTn; ++n)
        geom = geom && (fabsf(a[n] - (float)(n + 1) * a0) <= 1e-4f * fabsf(a[n]));
    float h[NSTn];
#pragma unroll
    for (int n = 0; n < NSTn; ++n) h[n] = 0.f;

    size_t base = (size_t)b * slen;
    int s0 = rev ? slen - 1 : 0;
    float uv_nx = u[(base + s0) * ustr + c];
    float z_nx  = xz[(base + s0) * xzs + DIi + c];
    float xdreg = (c < 40) ? xdbl[(base + s0) * 40 + c] : 0.f;

    for (int step = 0; step < slen; ++step) {
        int s = rev ? slen - 1 - step : step;
        int buf = step & 1;
        if (c < 40) sxd[buf][c] = xdreg;
        float uv = uv_nx, zv = z_nx;
        __syncthreads();
        if (step + 1 < slen) {
            int sn = rev ? s - 1 : s + 1;
            if (c < 40) xdreg = xdbl[(base + sn) * 40 + c];
            uv_nx = u[(base + sn) * ustr + c];
            z_nx  = xz[(base + sn) * xzs + DIi + c];
        }
        const float* xd = sxd[buf];
        float dtacc = dtbr;
#pragma unroll
        for (int q = 0; q < DTRr; ++q) dtacc = fmaf(xd[q], dtwr[q], dtacc);
        float dtv = (dtacc > 20.f) ? dtacc : __logf(1.f + __expf(dtacc));
        float du = dtv * uv;
        float ysum = 0.f;
        if (geom) {
            float w = __expf(dtv * a0);
            float e = 1.f;
#pragma unroll
            for (int n = 0; n < NSTn; ++n) {
                e *= w;
                h[n] = fmaf(h[n], e, du * xd[8 + n]);
                ysum = fmaf(h[n], xd[24 + n], ysum);
            }
        } else {
#pragma unroll
            for (int n = 0; n < NSTn; ++n) {
                float e = __expf(dtv * a[n]);
                h[n] = fmaf(h[n], e, du * xd[8 + n]);
                ysum = fmaf(h[n], xd[24 + n], ysum);
            }
        }
        float sg = 1.f / (1.f + __expf(-zv));
        y[(base + s) * ystr + c] = (ysum + uv * dss) * (zv * sg);
    }
}

// ======================= fused combine + LN (+transpose), float4 ==========
struct P5 { const float* p[5]; };

template <int TRANS, int NA, int NB>
__global__ void k_combineln(P5 pa, const float* __restrict__ ra,
                            P5 pb, const float* __restrict__ rb,
                            const float* __restrict__ w, const float* __restrict__ bia,
                            float* __restrict__ comb, float* __restrict__ normout) {
    __shared__ float ca[5], cb2[5];
    if (threadIdx.x == 0) {
        float mx = -1e30f;
#pragma unroll
        for (int i = 0; i < NA; ++i) mx = fmaxf(mx, ra[i]);
        float s = 0.f;
#pragma unroll
        for (int i = 0; i < NA; ++i) { ca[i] = __expf(ra[i] - mx); s += ca[i]; }
#pragma unroll
        for (int i = 0; i < NA; ++i) ca[i] /= s;
        mx = -1e30f;
#pragma unroll
        for (int i = 0; i < NB; ++i) mx = fmaxf(mx, rb[i]);
        s = 0.f;
#pragma unroll
        for (int i = 0; i < NB; ++i) { cb2[i] = __expf(rb[i] - mx); s += cb2[i]; }
#pragma unroll
        for (int i = 0; i < NB; ++i) cb2[i] /= s;
    }
    __syncthreads();
    int warp = threadIdx.x >> 5, lane = threadIdx.x & 31;
    int row = blockIdx.x * 4 + warp;
    if (row >= TT) return;
    int irow = row;
    if (TRANS) {
        int m = row & 31;
        int bn = row >> 5;
        int n = bn % Nn, b = bn / Nn;
        irow = (b * Mm + m) * Nn + n;
    }
    float wa[5], wb[5];
#pragma unroll
    for (int j = 0; j < NA; ++j) wa[j] = ca[j];
#pragma unroll
    for (int j = 0; j < NB; ++j) wb[j] = cb2[j];

    size_t ibase = (size_t)irow * Dd + lane * 4;
    float v[4] = {0.f, 0.f, 0.f, 0.f};
#pragma unroll
    for (int j = 0; j < NA; ++j) {
        float4 t = *reinterpret_cast<const float4*>(pa.p[j] + ibase);
        v[0] = fmaf(wa[j], t.x, v[0]); v[1] = fmaf(wa[j], t.y, v[1]);
        v[2] = fmaf(wa[j], t.z, v[2]); v[3] = fmaf(wa[j], t.w, v[3]);
    }
#pragma unroll
    for (int j = 0; j < NB; ++j) {
        float4 t = *reinterpret_cast<const float4*>(pb.p[j] + ibase);
        v[0] = fmaf(wb[j], t.x, v[0]); v[1] = fmaf(wb[j], t.y, v[1]);
        v[2] = fmaf(wb[j], t.z, v[2]); v[3] = fmaf(wb[j], t.w, v[3]);
    }
    *reinterpret_cast<float4*>(comb + ibase) = make_float4(v[0], v[1], v[2], v[3]);

    float s = v[0] + v[1] + v[2] + v[3];
#pragma unroll
    for (int o = 16; o; o >>= 1) s += __shfl_xor_sync(0xffffffffu, s, o);
    float mu = s * (1.f / Dd);
    float q0 = 0.f;
#pragma unroll
    for (int q = 0; q < 4; ++q) { v[q] -= mu; q0 += v[q] * v[q]; }
#pragma unroll
    for (int o = 16; o; o >>= 1) q0 += __shfl_xor_sync(0xffffffffu, q0, o);
    float r = rsqrtf(q0 * (1.f / Dd) + 1e-5f);
    float4 wv = *reinterpret_cast<const float4*>(w + lane * 4);
    float4 bv = *reinterpret_cast<const float4*>(bia + lane * 4);
    float4 ov;
    ov.x = v[0] * r * wv.x + bv.x;
    ov.y = v[1] * r * wv.y + bv.y;
    ov.z = v[2] * r * wv.z + bv.z;
    ov.w = v[3] * r * wv.w + bv.w;
    *reinterpret_cast<float4*>(normout + (size_t)row * Dd + lane * 4) = ov;
}

// ======================= fused Norm2D (LN over D, then LN over N) =======================
// One block per (b,m) series: stage 63x128 tile in smem, both LNs in-place.
__global__ __launch_bounds__(256) void k_norm2d(const float* __restrict__ x,
                                                const float* __restrict__ w1,
                                                const float* __restrict__ b1,
                                                const float* __restrict__ w2,
                                                const float* __restrict__ b2,
                                                float* __restrict__ out) {
    __shared__ float tile[Nn * Dd];
    int bm = blockIdx.x;
    int tid = threadIdx.x;
    const float* src = x + (size_t)bm * Nn * Dd;
    for (int i = tid; i < Nn * Dd; i += 256)
        tile[i] = src[i];
    __syncthreads();

    // LN over D, warp-per-row (identical reduction order to k_ln)
    int warp = tid >> 5, lane = tid & 31;
    for (int n = warp; n < Nn; n += 8) {
        float* row = &tile[n * Dd];
        float v0 = row[lane], v1 = row[lane + 32], v2 = row[lane + 64], v3 = row[lane + 96];
        float s = v0 + v1 + v2 + v3;
#pragma unroll
        for (int o = 16; o; o >>= 1) s += __shfl_xor_sync(0xffffffffu, s, o);
        float mu = s * (1.f / Dd);
        float d0 = v0 - mu, d1 = v1 - mu, d2 = v2 - mu, d3 = v3 - mu;
        float q = d0 * d0 + d1 * d1 + d2 * d2 + d3 * d3;
#pragma unroll
        for (int o = 16; o; o >>= 1) q += __shfl_xor_sync(0xffffffffu, q, o);
        float r = rsqrtf(q * (1.f / Dd) + 1e-5f);
        row[lane]      = d0 * r * w1[lane]      + b1[lane];
        row[lane + 32] = d1 * r * w1[lane + 32] + b1[lane + 32];
        row[lane + 64] = d2 * r * w1[lane + 64] + b1[lane + 64];
        row[lane + 96] = d3 * r * w1[lane + 96] + b1[lane + 96];
    }
    __syncthreads();

    // LN over N, thread-per-column (identical reduction order to k_ln_n)
    if (tid < Dd) {
        int d = tid;
        float s = 0.f, q = 0.f;
        for (int n = 0; n < Nn; ++n) { float v = tile[n * Dd + d]; s += v; q += v * v; }
        float mu = s * (1.f / Nn);
        float var = q * (1.f / Nn) - mu * mu;
        if (var < 0.f) var = 0.f;
        float r = rsqrtf(var + 1e-5f);
        float* ob = out + (size_t)bm * Nn * Dd + d;
        for (int n = 0; n < Nn; ++n)
            ob[(size_t)n * Dd] = (tile[n * Dd + d] - mu) * r * w2[n] + b2[n];
    }
}

// ======================= other supporting kernels =======================

__global__ void k_stats(const float* __restrict__ x, float* __restrict__ mean,
                        float* __restrict__ stdv, float* __restrict__ xn) {
    int bm = blockIdx.x;
    int b = bm >> 5, m = bm & 31;
    int tid = threadIdx.x;
    float s = 0.f, sq = 0.f;
    for (int l = tid; l < Ll; l += 256) {
        float v = x[((size_t)b * Ll + l) * Mm + m];
        s += v; sq += v * v;
    }
    __shared__ float sh1[256], sh2[256];
    sh1[tid] = s; sh2[tid] = sq;
    __syncthreads();
    for (int o = 128; o; o >>= 1) {
        if (tid < o) { sh1[tid] += sh1[tid + o]; sh2[tid] += sh2[tid + o]; }
        __syncthreads();
    }
    __shared__ float smu, ssd;
    if (tid == 0) {
        float mu = sh1[0] / (float)Ll;
        float var = (sh2[0] - (float)Ll * mu * mu) / (float)(Ll - 1);
        if (var < 0.f) var = 0.f;
        float sd = sqrtf(var) + 1e-5f;
        smu = mu; ssd = sd;
        mean[bm] = mu; stdv[bm] = sd;
    }
    __syncthreads();
    float inv = 1.f / ssd;
    float mu = smu;
    for (int l = tid; l < Ll; l += 256) {
        xn[(size_t)bm * Ll + l] = (x[((size_t)b * Ll + l) * Mm + m] - mu) * inv;
    }
}

__global__ void k_patch(const float* __restrict__ xn, const float* __restrict__ pw,
                        const float* __restrict__ pb, const float* __restrict__ pos,
                        float* __restrict__ h) {
    int blk = blockIdx.x;
    int n = blk % Nn, bm = blk / Nn;
    int d = threadIdx.x;
    __shared__ float xs[Pp];
    if (d < Pp) xs[d] = xn[(size_t)bm * Ll + n * Sss + d];
    __syncthreads();
    float acc = pb[d];
#pragma unroll
    for (int p = 0; p < Pp; ++p) acc = fmaf(xs[p], pw[d * Pp + p], acc);
    acc += pos[n * Dd + d];
    h[(size_t)blk * Dd + d] = acc;
}

__global__ void k_repack_all(const float* __restrict__ outw, float* __restrict__ wp) {
    int idx = blockIdx.x * 256 + threadIdx.x;
    if (idx >= 4 * 128 * 256) return;
    int lyr = idx >> 15, rem = idx & 32767;
    int d = rem >> 8, k = rem & 255;
    size_t o = (size_t)lyr * 65536 + d * 512 + k;
    wp[o]       = outw[(size_t)(lyr * 3 + 1) * 32768 + d * 256 + k];
    wp[o + 256] = outw[(size_t)(lyr * 3 + 2) * 32768 + d * 256 + k];
}

__global__ void k_headred(const float* __restrict__ hp, const float* __restrict__ hb,
                          const float* __restrict__ mean, const float* __restrict__ stdv,
                          float* __restrict__ out) {
    int idx = blockIdx.x * 256 + threadIdx.x;
    if (idx >= Bb * PREDp * Mm) return;
    int m = idx % Mm;
    int p = (idx / Mm) % PREDp;
    int b = idx / (Mm * PREDp);
    int bm = b * Mm + m;
    float s = 0.f;
#pragma unroll 3
    for (int z = 0; z < KSPLIT; ++z)
        s += hp[(size_t)z * BMr * PREDp + (size_t)bm * PREDp + p];
    out[idx] = (s + hb[p]) * stdv[bm] + mean[bm];
}

// ======================= host orchestration =======================

extern "C" void kernel_launch(void* const* d_in, const int* in_sizes, int n_in,
                              void* d_out, int out_size) {
    (void)in_sizes; (void)n_in; (void)out_size;
    const float* x      = (const float*)d_in[0];
    const float* patchw = (const float*)d_in[1];
    const float* patchb = (const float*)d_in[2];
    const float* pos    = (const float*)d_in[3];
    const float* alpha  = (const float*)d_in[4];
    const float* beta   = (const float*)d_in[5];
    const float* theta  = (const float*)d_in[6];
    const float* gma    = (const float*)d_in[7];
    const float* tnw    = (const float*)d_in[8];
    const float* tnb    = (const float*)d_in[9];
    const float* cnw    = (const float*)d_in[10];
    const float* cnb    = (const float*)d_in[11];
    const float* inw    = (const float*)d_in[12];
    const float* cvw    = (const float*)d_in[13];
    const float* cvb    = (const float*)d_in[14];
    const float* xpw    = (const float*)d_in[15];
    const float* dtw    = (const float*)d_in[16];
    const float* dtbv   = (const float*)d_in[17];
    const float* alog   = (const float*)d_in[18];
    const float* dssm   = (const float*)d_in[19];
    const float* outw   = (const float*)d_in[20];
    const float* n2w1   = (const float*)d_in[21];
    const float* n2b1   = (const float*)d_in[22];
    const float* n2w2   = (const float*)d_in[23];
    const float* n2b2   = (const float*)d_in[24];
    const float* headw  = (const float*)d_in[25];
    const float* headb  = (const float*)d_in[26];

    float *p_y, *p_xn, *p_mean, *p_std, *p_tokin, *p_norm, *p_chr;
    float *p_xz, *p_u, *p_xdbl, *p_ys, *p_headp, *p_wpack;
    cudaGetSymbolAddress((void**)&p_y,     g_y);
    cudaGetSymbolAddress((void**)&p_xn,    g_xn);
    cudaGetSymbolAddress((void**)&p_mean,  g_mean);
    cudaGetSymbolAddress((void**)&p_std,   g_std);
    cudaGetSymbolAddress((void**)&p_tokin, g_tokin);
    cudaGetSymbolAddress((void**)&p_norm,  g_norm);
    cudaGetSymbolAddress((void**)&p_chr,   g_chr);
    cudaGetSymbolAddress((void**)&p_xz,    g_xz);
    cudaGetSymbolAddress((void**)&p_u,     g_u);
    cudaGetSymbolAddress((void**)&p_xdbl,  g_xdbl);
    cudaGetSymbolAddress((void**)&p_ys,    g_ys);
    cudaGetSymbolAddress((void**)&p_headp, g_headp);
    cudaGetSymbolAddress((void**)&p_wpack, g_wpack);

    float* yT[5]; float* yC[5];
    yT[0] = p_y; yC[0] = p_y;
    for (int i = 1; i <= 4; ++i) {
        yT[i] = p_y + (size_t)i * TT * Dd;
        yC[i] = p_y + (size_t)(4 + i) * TT * Dd;
    }

    k_repack_all<<<512, 256>>>(outw, p_wpack);
    k_stats<<<BMr, 256>>>(x, p_mean, p_std, p_xn);
    k_patch<<<TT, Dd>>>(p_xn, patchw, patchb, pos, p_y);

    const int GY = TT / 128;        // 252
    const int CONVG = (TT * DIi + 255) / 256;

    for (int l = 0; l < NLl; ++l) {
        // ---- token mixing ----
        P5 pa = {}, pb = {};
        for (int i = 0; i <= l; ++i) { pa.p[i] = yT[i]; pb.p[i] = yC[i]; }
        switch (l) {
            case 0: k_combineln<0, 1, 1><<<TT / 4, 128>>>(pa, alpha + l * NLl, pb, beta + l * NLl,
                        tnw + l * Dd, tnb + l * Dd, p_tokin, p_norm); break;
            case 1: k_combineln<0, 2, 2><<<TT / 4, 128>>>(pa, alpha + l * NLl, pb, beta + l * NLl,
                        tnw + l * Dd, tnb + l * Dd, p_tokin, p_norm); break;
            case 2: k_combineln<0, 3, 3><<<TT / 4, 128>>>(pa, alpha + l * NLl, pb, beta + l * NLl,
                        tnw + l * Dd, tnb + l * Dd, p_tokin, p_norm); break;
            default: k_combineln<0, 4, 4><<<TT / 4, 128>>>(pa, alpha + l * NLl, pb, beta + l * NLl,
                        tnw + l * Dd, tnb + l * Dd, p_tokin, p_norm); break;
        }
        {
            size_t lr = (size_t)(l * 3 + 0);
            k_mma<512><<<dim3(8, GY, 1), 256>>>(p_norm, inw + lr * 2 * DIi * Dd, p_xz,
                                                nullptr, Dd, Dd, Dd, 0);
            k_conv<<<dim3(CONVG, 1), 256>>>(p_xz, 512, cvw + lr * DIi * DCc, cvb + lr * DIi,
                                            p_u, 256, BMr, Nn);
            k_mma<40><<<dim3(1, GY, 1), 256>>>(p_u, xpw + lr * 40 * DIi, p_xdbl,
                                               nullptr, DIi, 256, DIi, 0);
            k_scan<<<dim3(BMr, 1), 256>>>(p_xz, 512, p_xdbl, 0, p_u, 256,
                                          dtw + lr * DIi * DTRr, dtbv + lr * DIi,
                                          alog + lr * DIi * NSTn, dssm + lr * DIi,
                                          p_ys, 256, Nn);
            k_mma<128><<<dim3(2, GY, 1), 256>>>(p_ys, outw + lr * Dd * DIi, yT[l + 1],
                                                p_tokin, DIi, DIi, DIi, 2);
        }

        // ---- channel mixing (fwd+bwd fused; transposed epilogue writes yC) ----
        P5 pc = {}, pd = {};
        for (int i = 0; i <= l + 1; ++i) pc.p[i] = yT[i];
        for (int i = 0; i <= l; ++i)     pd.p[i] = yC[i];
        switch (l) {
            case 0: k_combineln<1, 2, 1><<<TT / 4, 128>>>(pc, theta + l * (NLl + 1), pd, gma + l * NLl,
                        cnw + l * Dd, cnb + l * Dd, p_tokin, p_chr); break;
            case 1: k_combineln<1, 3, 2><<<TT / 4, 128>>>(pc, theta + l * (NLl + 1), pd, gma + l * NLl,
                        cnw + l * Dd, cnb + l * Dd, p_tokin, p_chr); break;
            case 2: k_combineln<1, 4, 3><<<TT / 4, 128>>>(pc, theta + l * (NLl + 1), pd, gma + l * NLl,
                        cnw + l * Dd, cnb + l * Dd, p_tokin, p_chr); break;
            default: k_combineln<1, 5, 4><<<TT / 4, 128>>>(pc, theta + l * (NLl + 1), pd, gma + l * NLl,
                        cnw + l * Dd, cnb + l * Dd, p_tokin, p_chr); break;
        }
        {
            size_t lr = (size_t)(l * 3 + 1);       // role 1; role 2 contiguous after
            k_mma<1024><<<dim3(16, GY, 1), 256>>>(p_chr, inw + lr * 2 * DIi * Dd, p_xz,
                                                  nullptr, Dd, Dd, Dd, 0);
            k_conv<<<dim3(CONVG, 2), 256>>>(p_xz, 1024, cvw + lr * DIi * DCc, cvb + lr * DIi,
                                            p_u, 512, BNb, Mm);
            // dual-role x_proj: blockIdx.z selects role (A+=z*256, B+=z*40*K, C+=z*TT*40)
            k_mma<40><<<dim3(1, GY, 2), 256>>>(p_u, xpw + lr * 40 * DIi, p_xdbl,
                                               nullptr, DIi, 512, DIi, 8);
            k_scan<<<dim3(BNb, 2), 256>>>(p_xz, 1024, p_xdbl, (size_t)TT * 40, p_u, 512,
                                          dtw + lr * DIi * DTRr, dtbv + lr * DIi,
                                          alog + lr * DIi * NSTn, dssm + lr * DIi,
                                          p_ys, 512, Mm);
            k_mma<128><<<dim3(2, GY, 1), 256>>>(p_ys, p_wpack + (size_t)l * 65536, yC[l + 1],
                                                p_tokin, 512, 512, 512, 2 | 4);
        }
    }

    // fused Norm2D (LN over D then LN over N) -> head GEMM A input
    k_norm2d<<<BMr, 256>>>(yC[4], n2w1, n2b1, n2w2, n2b2, p_norm);
    k_mma<96><<<dim3(2, 4, KSPLIT), 256>>>(p_norm, headw, p_headp, nullptr,
                                           Nn * Dd, Nn * Dd, 384, 0);
    k_headred<<<(Bb * PREDp * Mm + 255) / 256, 256>>>(p_headp, headb, p_mean, p_std,
                                                      (float*)d_out);
}

// round 16
// speedup vs baseline: 1.0080x; 1.0080x over previous
#include <cuda_runtime.h>
#include <cuda_bf16.h>
#include <math.h>
#include <stdint.h>

// ---- problem dims ----
#define Bb   16
#define Ll   512
#define Mm   32
#define PREDp 96
#define Pp   16
#define Sss  8
#define Dd   128
#define NSTn 16
#define DCc  4
#define NLl  4
#define Nn   63
#define DIi  256
#define DTRr 8
#define BMr  512
#define TT   32256        // = 512*63 = 1008*32 = 252*128
#define BNb  1008
#define KSPLIT 21         // head GEMM split-K slices (8064 = 21*384)

// ---- static device scratch ----
__device__ float g_y[9][(size_t)TT * Dd];
__device__ float g_xn[(size_t)BMr * Ll];
__device__ float g_mean[BMr];
__device__ float g_std[BMr];
__device__ float g_tokin[(size_t)TT * Dd];
__device__ float g_xz[(size_t)TT * 1024];      // up to 2 roles x (xi|z)
__device__ float g_u[(size_t)TT * 512];        // conv+silu output, up to 2 roles
__device__ float g_xdbl[(size_t)TT * 80];      // x_proj output, up to 2 roles x 40
__device__ float g_ys[(size_t)TT * 512];       // scan output, up to 2 roles
__device__ float g_tmp[(size_t)TT * Dd];
__device__ float g_norm[(size_t)TT * Dd];
__device__ float g_chr[(size_t)TT * Dd];
__device__ float g_wpack[4 * 128 * 512];
__device__ float g_headp[(size_t)KSPLIT * BMr * PREDp];

// ======================= warp-mma bf16-split GEMM =======================
// C[M,NT] = A[M,K] @ Bw[NT,K]^T, fp32 in/out, bf16 hi/lo split (3 HMMA terms).
// A row stride = lda (>= K), B row stride = K.
// grid = (ceil(NT/64), M/128, nz), block = 256 (8 warps of 32x32 tiles).
// flags: 1 = accumulate into C, 2 = add R, 4 = transposed epilogue,
//        8 = dual-role mode (blockIdx.z selects role: A+=z*256, B+=z*40*K, C+=z*TT*40).

#define SASTR 40   // smem row stride (bf16): 80B -> conflict-free ldmatrix

__device__ __forceinline__ uint32_t smem_u32(const void* p) {
    return (uint32_t)__cvta_generic_to_shared(p);
}

__device__ __forceinline__ void mma16816(float* d, const uint32_t* a, const uint32_t* b) {
    asm volatile(
        "mma.sync.aligned.m16n8k16.row.col.f32.bf16.bf16.f32 "
        "{%0,%1,%2,%3},{%4,%5,%6,%7},{%8,%9},{%0,%1,%2,%3};"
        : "+f"(d[0]), "+f"(d[1]), "+f"(d[2]), "+f"(d[3])
        : "r"(a[0]), "r"(a[1]), "r"(a[2]), "r"(a[3]), "r"(b[0]), "r"(b[1]));
}

__device__ __forceinline__ void ldm_x4(uint32_t* r, uint32_t a) {
    asm volatile("ldmatrix.sync.aligned.m8n8.x4.shared.b16 {%0,%1,%2,%3}, [%4];"
                 : "=r"(r[0]), "=r"(r[1]), "=r"(r[2]), "=r"(r[3]) : "r"(a));
}

union BH2 { __nv_bfloat16 h[2]; uint32_t u; };

__device__ __forceinline__ int trow(int row) {
    int m = row & 31;
    int bn = row >> 5;
    int n = bn % Nn, b = bn / Nn;
    return (b * Mm + m) * Nn + n;
}

template <int NT>
__global__ __launch_bounds__(256) void k_mma(const float* __restrict__ A,
                                             const float* __restrict__ Bw,
                                             float* __restrict__ C,
                                             const float* __restrict__ R,
                                             int K, int lda, int klen, int flags) {
    __shared__ __nv_bfloat16 sA[2][128 * SASTR];
    __shared__ __nv_bfloat16 sB[2][64 * SASTR];

    int tid = threadIdx.x;
    int warp = tid >> 5, lane = tid & 31;
    int gq = lane >> 2, tig = lane & 3;
    int warpM = warp >> 1, warpN = warp & 1;
    int m0 = blockIdx.y * 128;
    int n0 = blockIdx.x * 64;
    int kbeg;
    if (flags & 8) {
        A  += (size_t)blockIdx.z * 256;
        Bw += (size_t)blockIdx.z * 40 * K;
        C  += (size_t)blockIdx.z * ((size_t)TT * 40);
        kbeg = 0;
    } else {
        kbeg = blockIdx.z * klen;
        C += (size_t)blockIdx.z * ((size_t)gridDim.y * 128) * NT;
    }

    int g = lane >> 3, rr = lane & 7;
    int aoff = (warpM * 32 + (g & 1) * 8 + rr) * SASTR + (g >> 1) * 8;
    int boff = (warpN * 32 + (g >> 1) * 8 + rr) * SASTR + (g & 1) * 8;
    uint32_t sA0 = smem_u32(&sA[0][0]), sA1 = smem_u32(&sA[1][0]);
    uint32_t sB0 = smem_u32(&sB[0][0]), sB1 = smem_u32(&sB[1][0]);

    float acc[2][4][4];
#pragma unroll
    for (int i = 0; i < 2; ++i)
#pragma unroll
        for (int j = 0; j < 4; ++j)
#pragma unroll
            for (int r = 0; r < 4; ++r) acc[i][j][r] = 0.f;

    float4 ra[4], rb[2];

    auto ldA = [&](int k0) {
#pragma unroll
        for (int t = 0; t < 4; ++t) {
            int gg = tid + t * 256;
            int row = gg >> 3, c = (gg & 7) << 2;
            ra[t] = *reinterpret_cast<const float4*>(A + (size_t)(m0 + row) * lda + k0 + c);
        }
    };
    auto ldB = [&](int k0) {
#pragma unroll
        for (int t = 0; t < 2; ++t) {
            int gg = tid + t * 256;
            int row = gg >> 3, c = (gg & 7) << 2;
            int grow = n0 + row;
            if ((NT & 63) == 0 || grow < NT)
                rb[t] = *reinterpret_cast<const float4*>(Bw + (size_t)grow * K + k0 + c);
            else
                rb[t] = make_float4(0.f, 0.f, 0.f, 0.f);
        }
    };

    ldA(kbeg); ldB(kbeg);
    int nch = klen >> 5;
    for (int ch = 0; ch < nch; ++ch) {
#pragma unroll
        for (int t = 0; t < 4; ++t) {
            int gg = tid + t * 256;
            int row = gg >> 3, c = (gg & 7) << 2;
            float v[4] = {ra[t].x, ra[t].y, ra[t].z, ra[t].w};
            BH2 h0, h1, l0, l1;
#pragma unroll
            for (int q = 0; q < 2; ++q) {
                h0.h[q] = __float2bfloat16(v[q]);
                l0.h[q] = __float2bfloat16(v[q] - __bfloat162float(h0.h[q]));
                h1.h[q] = __float2bfloat16(v[2 + q]);
                l1.h[q] = __float2bfloat16(v[2 + q] - __bfloat162float(h1.h[q]));
            }
            uint32_t* ph = reinterpret_cast<uint32_t*>(&sA[0][row * SASTR + c]);
            uint32_t* pl = reinterpret_cast<uint32_t*>(&sA[1][row * SASTR + c]);
            ph[0] = h0.u; ph[1] = h1.u; pl[0] = l0.u; pl[1] = l1.u;
        }
#pragma unroll
        for (int t = 0; t < 2; ++t) {
            int gg = tid + t * 256;
            int row = gg >> 3, c = (gg & 7) << 2;
            float v[4] = {rb[t].x, rb[t].y, rb[t].z, rb[t].w};
            BH2 h0, h1, l0, l1;
#pragma unroll
            for (int q = 0; q < 2; ++q) {
                h0.h[q] = __float2bfloat16(v[q]);
                l0.h[q] = __float2bfloat16(v[q] - __bfloat162float(h0.h[q]));
                h1.h[q] = __float2bfloat16(v[2 + q]);
                l1.h[q] = __float2bfloat16(v[2 + q] - __bfloat162float(h1.h[q]));
            }
            uint32_t* ph = reinterpret_cast<uint32_t*>(&sB[0][row * SASTR + c]);
            uint32_t* pl = reinterpret_cast<uint32_t*>(&sB[1][row * SASTR + c]);
            ph[0] = h0.u; ph[1] = h1.u; pl[0] = l0.u; pl[1] = l1.u;
        }
        __syncthreads();
        if (ch + 1 < nch) { ldA(kbeg + ((ch + 1) << 5)); ldB(kbeg + ((ch + 1) << 5)); }

#pragma unroll
        for (int kk = 0; kk < 2; ++kk) {
            int kb = kk * 16;
            uint32_t ah[2][4], al[2][4];
            ldm_x4(ah[0], sA0 + (uint32_t)(aoff + kb) * 2);
            ldm_x4(ah[1], sA0 + (uint32_t)(aoff + 16 * SASTR + kb) * 2);
            ldm_x4(al[0], sA1 + (uint32_t)(aoff + kb) * 2);
            ldm_x4(al[1], sA1 + (uint32_t)(aoff + 16 * SASTR + kb) * 2);
            uint32_t bh[4][2], bl[4][2], t0[4], t1[4];
            ldm_x4(t0, sB0 + (uint32_t)(boff + kb) * 2);
            ldm_x4(t1, sB0 + (uint32_t)(boff + 16 * SASTR + kb) * 2);
            bh[0][0] = t0[0]; bh[0][1] = t0[1]; bh[1][0] = t0[2]; bh[1][1] = t0[3];
            bh[2][0] = t1[0]; bh[2][1] = t1[1]; bh[3][0] = t1[2]; bh[3][1] = t1[3];
            ldm_x4(t0, sB1 + (uint32_t)(boff + kb) * 2);
            ldm_x4(t1, sB1 + (uint32_t)(boff + 16 * SASTR + kb) * 2);
            bl[0][0] = t0[0]; bl[0][1] = t0[1]; bl[1][0] = t0[2]; bl[1][1] = t0[3];
            bl[2][0] = t1[0]; bl[2][1] = t1[1]; bl[3][0] = t1[2]; bl[3][1] = t1[3];
#pragma unroll
            for (int i = 0; i < 2; ++i)
#pragma unroll
                for (int j = 0; j < 4; ++j) {
                    mma16816(acc[i][j], ah[i], bh[j]);
                    mma16816(acc[i][j], ah[i], bl[j]);
                    mma16816(acc[i][j], al[i], bh[j]);
                }
        }
        __syncthreads();
    }

#pragma unroll
    for (int i = 0; i < 2; ++i) {
        int grow = m0 + warpM * 32 + i * 16 + gq;
        int orow0 = (flags & 4) ? trow(grow) : grow;
        int orow1 = (flags & 4) ? trow(grow + 8) : (grow + 8);
#pragma unroll
        for (int j = 0; j < 4; ++j) {
            int gcol = n0 + warpN * 32 + j * 8 + 2 * tig;
            if ((NT & 63) != 0 && gcol >= NT) continue;
            size_t o0 = (size_t)orow0 * NT + gcol;
            size_t o1 = (size_t)orow1 * NT + gcol;
            float2 v0 = make_float2(acc[i][j][0], acc[i][j][1]);
            float2 v1 = make_float2(acc[i][j][2], acc[i][j][3]);
            if (flags & 2) {
                float2 t0 = *reinterpret_cast<const float2*>(R + o0);
                float2 t1 = *reinterpret_cast<const float2*>(R + o1);
                v0.x += t0.x; v0.y += t0.y; v1.x += t1.x; v1.y += t1.y;
            }
            if (flags & 1) {
                float2 t0 = *reinterpret_cast<const float2*>(C + o0);
                float2 t1 = *reinterpret_cast<const float2*>(C + o1);
                v0.x += t0.x; v0.y += t0.y; v1.x += t1.x; v1.y += t1.y;
            }
            *reinterpret_cast<float2*>(C + o0) = v0;
            *reinterpret_cast<float2*>(C + o1) = v1;
        }
    }
}

// ======================= conv + SiLU (elementwise, multi-role) =======================
__global__ void k_conv(const float* __restrict__ xz, int xzs,
                       const float* __restrict__ cw, const float* __restrict__ cb,
                       float* __restrict__ u, int ustr, int batch, int slen) {
    int r = blockIdx.y;
    int rev = r;
    xz += (size_t)r * 512;
    cw += (size_t)r * DIi * DCc;
    cb += (size_t)r * DIi;
    u  += (size_t)r * 256;
    int idx = blockIdx.x * 256 + threadIdx.x;
    int total = batch * slen * DIi;
    if (idx >= total) return;
    int c = idx & 255;
    int row = idx >> 8;
    int s = row % slen, b = row / slen;
    float acc = cb[c];
#pragma unroll
    for (int k = 0; k < DCc; ++k) {
        int t = rev ? (s + 3 - k) : (s + k - 3);
        if (t >= 0 && t < slen)
            acc = fmaf(cw[c * DCc + k], xz[((size_t)(b * slen + t)) * xzs + c], acc);
    }
    u[(size_t)row * ustr + c] = acc / (1.f + __expf(-acc));
}

// ======================= scan (no matvec, one sync/step, multi-role) =======================
__global__ __launch_bounds__(256) void k_scan(
    const float* __restrict__ xz, int xzs,
    const float* __restrict__ xdbl, size_t xdstr,
    const float* __restrict__ u, int ustr,
    const float* __restrict__ dtw, const float* __restrict__ dtb,
    const float* __restrict__ alog, const float* __restrict__ dssm,
    float* __restrict__ y, int ystr, int slen) {
    __shared__ float sxd[2][40];

    int r = blockIdx.y;
    int rev = r;
    xz   += (size_t)r * 512;
    xdbl += (size_t)r * xdstr;
    u    += (size_t)r * 256;
    dtw  += (size_t)r * DIi * DTRr;
    dtb  += (size_t)r * DIi;
    alog += (size_t)r * DIi * NSTn;
    dssm += (size_t)r * DIi;
    y    += (size_t)r * 256;

    int c = threadIdx.x;
    int b = blockIdx.x;

    float dtwr[DTRr];
#pragma unroll
    for (int q = 0; q < DTRr; ++q) dtwr[q] = dtw[c * DTRr + q];
    float dtbr = dtb[c];
    float dss = dssm[c];

    float a[NSTn];
#pragma unroll
    for (int n = 0; n < NSTn; ++n) a[n] = -__expf(alog[c * NSTn + n]);
    float a0 = a[0];
    bool geom = true;
#pragma unroll
    for (int n = 1; n < NSTn; ++n)
        geom = geom && (fabsf(a[n] - (float)(n + 1) * a0) <= 1e-4f * fabsf(a[n]));
    float h[NSTn];
#pragma unroll
    for (int n = 0; n < NSTn; ++n) h[n] = 0.f;

    size_t base = (size_t)b * slen;
    int s0 = rev ? slen - 1 : 0;
    float uv_nx = u[(base + s0) * ustr + c];
    float z_nx  = xz[(base + s0) * xzs + DIi + c];
    float xdreg = (c < 40) ? xdbl[(base + s0) * 40 + c] : 0.f;

    for (int step = 0; step < slen; ++step) {
        int s = rev ? slen - 1 - step : step;
        int buf = step & 1;
        if (c < 40) sxd[buf][c] = xdreg;
        float uv = uv_nx, zv = z_nx;
        __syncthreads();
        if (step + 1 < slen) {
            int sn = rev ? s - 1 : s + 1;
            if (c < 40) xdreg = xdbl[(base + sn) * 40 + c];
            uv_nx = u[(base + sn) * ustr + c];
            z_nx  = xz[(base + sn) * xzs + DIi + c];
        }
        const float* xd = sxd[buf];
        float dtacc = dtbr;
#pragma unroll
        for (int q = 0; q < DTRr; ++q) dtacc = fmaf(xd[q], dtwr[q], dtacc);
        float dtv = (dtacc > 20.f) ? dtacc : __logf(1.f + __expf(dtacc));
        float du = dtv * uv;
        float ysum = 0.f;
        if (geom) {
            float w = __expf(dtv * a0);
            float e = 1.f;
#pragma unroll
            for (int n = 0; n < NSTn; ++n) {
                e *= w;
                h[n] = fmaf(h[n], e, du * xd[8 + n]);
                ysum = fmaf(h[n], xd[24 + n], ysum);
            }
        } else {
#pragma unroll
            for (int n = 0; n < NSTn; ++n) {
                float e = __expf(dtv * a[n]);
                h[n] = fmaf(h[n], e, du * xd[8 + n]);
                ysum = fmaf(h[n], xd[24 + n], ysum);
            }
        }
        float sg = 1.f / (1.f + __expf(-zv));
        y[(base + s) * ystr + c] = (ysum + uv * dss) * (zv * sg);
    }
}

// ======================= fused combine + LN (+transpose), float4 ==========
struct P5 { const float* p[5]; };

template <int TRANS, int NA, int NB>
__global__ void k_combineln(P5 pa, const float* __restrict__ ra,
                            P5 pb, const float* __restrict__ rb,
                            const float* __restrict__ w, const float* __restrict__ bia,
                            float* __restrict__ comb, float* __restrict__ normout) {
    __shared__ float ca[5], cb2[5];
    if (threadIdx.x == 0) {
        float mx = -1e30f;
#pragma unroll
        for (int i = 0; i < NA; ++i) mx = fmaxf(mx, ra[i]);
        float s = 0.f;
#pragma unroll
        for (int i = 0; i < NA; ++i) { ca[i] = __expf(ra[i] - mx); s += ca[i]; }
#pragma unroll
        for (int i = 0; i < NA; ++i) ca[i] /= s;
        mx = -1e30f;
#pragma unroll
        for (int i = 0; i < NB; ++i) mx = fmaxf(mx, rb[i]);
        s = 0.f;
#pragma unroll
        for (int i = 0; i < NB; ++i) { cb2[i] = __expf(rb[i] - mx); s += cb2[i]; }
#pragma unroll
        for (int i = 0; i < NB; ++i) cb2[i] /= s;
    }
    __syncthreads();
    int warp = threadIdx.x >> 5, lane = threadIdx.x & 31;
    int row = blockIdx.x * 4 + warp;
    if (row >= TT) return;
    int irow = row;
    if (TRANS) {
        int m = row & 31;
        int bn = row >> 5;
        int n = bn % Nn, b = bn / Nn;
        irow = (b * Mm + m) * Nn + n;
    }
    float wa[5], wb[5];
#pragma unroll
    for (int j = 0; j < NA; ++j) wa[j] = ca[j];
#pragma unroll
    for (int j = 0; j < NB; ++j) wb[j] = cb2[j];

    size_t ibase = (size_t)irow * Dd + lane * 4;
    float v[4] = {0.f, 0.f, 0.f, 0.f};
#pragma unroll
    for (int j = 0; j < NA; ++j) {
        float4 t = *reinterpret_cast<const float4*>(pa.p[j] + ibase);
        v[0] = fmaf(wa[j], t.x, v[0]); v[1] = fmaf(wa[j], t.y, v[1]);
        v[2] = fmaf(wa[j], t.z, v[2]); v[3] = fmaf(wa[j], t.w, v[3]);
    }
#pragma unroll
    for (int j = 0; j < NB; ++j) {
        float4 t = *reinterpret_cast<const float4*>(pb.p[j] + ibase);
        v[0] = fmaf(wb[j], t.x, v[0]); v[1] = fmaf(wb[j], t.y, v[1]);
        v[2] = fmaf(wb[j], t.z, v[2]); v[3] = fmaf(wb[j], t.w, v[3]);
    }
    *reinterpret_cast<float4*>(comb + ibase) = make_float4(v[0], v[1], v[2], v[3]);

    float s = v[0] + v[1] + v[2] + v[3];
#pragma unroll
    for (int o = 16; o; o >>= 1) s += __shfl_xor_sync(0xffffffffu, s, o);
    float mu = s * (1.f / Dd);
    float q0 = 0.f;
#pragma unroll
    for (int q = 0; q < 4; ++q) { v[q] -= mu; q0 += v[q] * v[q]; }
#pragma unroll
    for (int o = 16; o; o >>= 1) q0 += __shfl_xor_sync(0xffffffffu, q0, o);
    float r = rsqrtf(q0 * (1.f / Dd) + 1e-5f);
    float4 wv = *reinterpret_cast<const float4*>(w + lane * 4);
    float4 bv = *reinterpret_cast<const float4*>(bia + lane * 4);
    float4 ov;
    ov.x = v[0] * r * wv.x + bv.x;
    ov.y = v[1] * r * wv.y + bv.y;
    ov.z = v[2] * r * wv.z + bv.z;
    ov.w = v[3] * r * wv.w + bv.w;
    *reinterpret_cast<float4*>(normout + (size_t)row * Dd + lane * 4) = ov;
}

// ======================= other supporting kernels =======================

__global__ void k_stats(const float* __restrict__ x, float* __restrict__ mean,
                        float* __restrict__ stdv, float* __restrict__ xn) {
    int bm = blockIdx.x;
    int b = bm >> 5, m = bm & 31;
    int tid = threadIdx.x;
    float s = 0.f, sq = 0.f;
    for (int l = tid; l < Ll; l += 256) {
        float v = x[((size_t)b * Ll + l) * Mm + m];
        s += v; sq += v * v;
    }
    __shared__ float sh1[256], sh2[256];
    sh1[tid] = s; sh2[tid] = sq;
    __syncthreads();
    for (int o = 128; o; o >>= 1) {
        if (tid < o) { sh1[tid] += sh1[tid + o]; sh2[tid] += sh2[tid + o]; }
        __syncthreads();
    }
    __shared__ float smu, ssd;
    if (tid == 0) {
        float mu = sh1[0] / (float)Ll;
        float var = (sh2[0] - (float)Ll * mu * mu) / (float)(Ll - 1);
        if (var < 0.f) var = 0.f;
        float sd = sqrtf(var) + 1e-5f;
        smu = mu; ssd = sd;
        mean[bm] = mu; stdv[bm] = sd;
    }
    __syncthreads();
    float inv = 1.f / ssd;
    float mu = smu;
    for (int l = tid; l < Ll; l += 256) {
        xn[(size_t)bm * Ll + l] = (x[((size_t)b * Ll + l) * Mm + m] - mu) * inv;
    }
}

__global__ void k_patch(const float* __restrict__ xn, const float* __restrict__ pw,
                        const float* __restrict__ pb, const float* __restrict__ pos,
                        float* __restrict__ h) {
    int blk = blockIdx.x;
    int n = blk % Nn, bm = blk / Nn;
    int d = threadIdx.x;
    __shared__ float xs[Pp];
    if (d < Pp) xs[d] = xn[(size_t)bm * Ll + n * Sss + d];
    __syncthreads();
    float acc = pb[d];
#pragma unroll
    for (int p = 0; p < Pp; ++p) acc = fmaf(xs[p], pw[d * Pp + p], acc);
    acc += pos[n * Dd + d];
    h[(size_t)blk * Dd + d] = acc;
}

__global__ void k_ln(const float* __restrict__ x, const float* __restrict__ w,
                     const float* __restrict__ bia, float* __restrict__ out, int rows) {
    int warp = threadIdx.x >> 5, lane = threadIdx.x & 31;
    int row = blockIdx.x * 4 + warp;
    if (row >= rows) return;
    const float* xr = x + (size_t)row * Dd;
    float v0 = xr[lane], v1 = xr[lane + 32], v2 = xr[lane + 64], v3 = xr[lane + 96];
    float s = v0 + v1 + v2 + v3;
#pragma unroll
    for (int o = 16; o; o >>= 1) s += __shfl_xor_sync(0xffffffffu, s, o);
    float mu = s * (1.f / Dd);
    float d0 = v0 - mu, d1 = v1 - mu, d2 = v2 - mu, d3 = v3 - mu;
    float q = d0 * d0 + d1 * d1 + d2 * d2 + d3 * d3;
#pragma unroll
    for (int o = 16; o; o >>= 1) q += __shfl_xor_sync(0xffffffffu, q, o);
    float r = rsqrtf(q * (1.f / Dd) + 1e-5f);
    float* orow = out + (size_t)row * Dd;
    orow[lane]      = d0 * r * w[lane]      + bia[lane];
    orow[lane + 32] = d1 * r * w[lane + 32] + bia[lane + 32];
    orow[lane + 64] = d2 * r * w[lane + 64] + bia[lane + 64];
    orow[lane + 96] = d3 * r * w[lane + 96] + bia[lane + 96];
}

__global__ void k_ln_n(const float* __restrict__ x, const float* __restrict__ w2,
                       const float* __restrict__ b2, float* __restrict__ out) {
    int idx = blockIdx.x * 256 + threadIdx.x;
    if (idx >= BMr * Dd) return;
    int d = idx & 127, bm = idx >> 7;
    const float* base = x + (size_t)bm * Nn * Dd + d;
    float s = 0.f, q = 0.f;
    for (int n = 0; n < Nn; ++n) { float v = base[(size_t)n * Dd]; s += v; q += v * v; }
    float mu = s * (1.f / Nn);
    float var = q * (1.f / Nn) - mu * mu;
    if (var < 0.f) var = 0.f;
    float r = rsqrtf(var + 1e-5f);
    float* ob = out + (size_t)bm * Nn * Dd + d;
    for (int n = 0; n < Nn; ++n)
        ob[(size_t)n * Dd] = (base[(size_t)n * Dd] - mu) * r * w2[n] + b2[n];
}

__global__ void k_repack_all(const float* __restrict__ outw, float* __restrict__ wp) {
    int idx = blockIdx.x * 256 + threadIdx.x;
    if (idx >= 4 * 128 * 256) return;
    int lyr = idx >> 15, rem = idx & 32767;
    int d = rem >> 8, k = rem & 255;
    size_t o = (size_t)lyr * 65536 + d * 512 + k;
    wp[o]       = outw[(size_t)(lyr * 3 + 1) * 32768 + d * 256 + k];
    wp[o + 256] = outw[(size_t)(lyr * 3 + 2) * 32768 + d * 256 + k];
}

__global__ void k_headred(const float* __restrict__ hp, const float* __restrict__ hb,
                          const float* __restrict__ mean, const float* __restrict__ stdv,
                          float* __restrict__ out) {
    int idx = blockIdx.x * 256 + threadIdx.x;
    if (idx >= Bb * PREDp * Mm) return;
    int m = idx % Mm;
    int p = (idx / Mm) % PREDp;
    int b = idx / (Mm * PREDp);
    int bm = b * Mm + m;
    float s = 0.f;
#pragma unroll 3
    for (int z = 0; z < KSPLIT; ++z)
        s += hp[(size_t)z * BMr * PREDp + (size_t)bm * PREDp + p];
    out[idx] = (s + hb[p]) * stdv[bm] + mean[bm];
}

// ======================= host orchestration =======================

extern "C" void kernel_launch(void* const* d_in, const int* in_sizes, int n_in,
                              void* d_out, int out_size) {
    (void)in_sizes; (void)n_in; (void)out_size;
    const float* x      = (const float*)d_in[0];
    const float* patchw = (const float*)d_in[1];
    const float* patchb = (const float*)d_in[2];
    const float* pos    = (const float*)d_in[3];
    const float* alpha  = (const float*)d_in[4];
    const float* beta   = (const float*)d_in[5];
    const float* theta  = (const float*)d_in[6];
    const float* gma    = (const float*)d_in[7];
    const float* tnw    = (const float*)d_in[8];
    const float* tnb    = (const float*)d_in[9];
    const float* cnw    = (const float*)d_in[10];
    const float* cnb    = (const float*)d_in[11];
    const float* inw    = (const float*)d_in[12];
    const float* cvw    = (const float*)d_in[13];
    const float* cvb    = (const float*)d_in[14];
    const float* xpw    = (const float*)d_in[15];
    const float* dtw    = (const float*)d_in[16];
    const float* dtbv   = (const float*)d_in[17];
    const float* alog   = (const float*)d_in[18];
    const float* dssm   = (const float*)d_in[19];
    const float* outw   = (const float*)d_in[20];
    const float* n2w1   = (const float*)d_in[21];
    const float* n2b1   = (const float*)d_in[22];
    const float* n2w2   = (const float*)d_in[23];
    const float* n2b2   = (const float*)d_in[24];
    const float* headw  = (const float*)d_in[25];
    const float* headb  = (const float*)d_in[26];

    float *p_y, *p_xn, *p_mean, *p_std, *p_tokin, *p_norm, *p_chr;
    float *p_xz, *p_u, *p_xdbl, *p_ys, *p_tmp, *p_headp, *p_wpack;
    cudaGetSymbolAddress((void**)&p_y,     g_y);
    cudaGetSymbolAddress((void**)&p_xn,    g_xn);
    cudaGetSymbolAddress((void**)&p_mean,  g_mean);
    cudaGetSymbolAddress((void**)&p_std,   g_std);
    cudaGetSymbolAddress((void**)&p_tokin, g_tokin);
    cudaGetSymbolAddress((void**)&p_norm,  g_norm);
    cudaGetSymbolAddress((void**)&p_chr,   g_chr);
    cudaGetSymbolAddress((void**)&p_xz,    g_xz);
    cudaGetSymbolAddress((void**)&p_u,     g_u);
    cudaGetSymbolAddress((void**)&p_xdbl,  g_xdbl);
    cudaGetSymbolAddress((void**)&p_ys,    g_ys);
    cudaGetSymbolAddress((void**)&p_tmp,   g_tmp);
    cudaGetSymbolAddress((void**)&p_headp, g_headp);
    cudaGetSymbolAddress((void**)&p_wpack, g_wpack);

    float* yT[5]; float* yC[5];
    yT[0] = p_y; yC[0] = p_y;
    for (int i = 1; i <= 4; ++i) {
        yT[i] = p_y + (size_t)i * TT * Dd;
        yC[i] = p_y + (size_t)(4 + i) * TT * Dd;
    }

    k_repack_all<<<512, 256>>>(outw, p_wpack);
    k_stats<<<BMr, 256>>>(x, p_mean, p_std, p_xn);
    k_patch<<<TT, Dd>>>(p_xn, patchw, patchb, pos, p_y);

    const int GY = TT / 128;        // 252
    const int CONVG = (TT * DIi + 255) / 256;

    for (int l = 0; l < NLl; ++l) {
        // ---- token mixing ----
        P5 pa = {}, pb = {};
        for (int i = 0; i <= l; ++i) { pa.p[i] = yT[i]; pb.p[i] = yC[i]; }
        switch (l) {
            case 0: k_combineln<0, 1, 1><<<TT / 4, 128>>>(pa, alpha + l * NLl, pb, beta + l * NLl,
                        tnw + l * Dd, tnb + l * Dd, p_tokin, p_norm); break;
            case 1: k_combineln<0, 2, 2><<<TT / 4, 128>>>(pa, alpha + l * NLl, pb, beta + l * NLl,
                        tnw + l * Dd, tnb + l * Dd, p_tokin, p_norm); break;
            case 2: k_combineln<0, 3, 3><<<TT / 4, 128>>>(pa, alpha + l * NLl, pb, beta + l * NLl,
                        tnw + l * Dd, tnb + l * Dd, p_tokin, p_norm); break;
            default: k_combineln<0, 4, 4><<<TT / 4, 128>>>(pa, alpha + l * NLl, pb, beta + l * NLl,
                        tnw + l * Dd, tnb + l * Dd, p_tokin, p_norm); break;
        }
        {
            size_t lr = (size_t)(l * 3 + 0);
            k_mma<512><<<dim3(8, GY, 1), 256>>>(p_norm, inw + lr * 2 * DIi * Dd, p_xz,
                                                nullptr, Dd, Dd, Dd, 0);
            k_conv<<<dim3(CONVG, 1), 256>>>(p_xz, 512, cvw + lr * DIi * DCc, cvb + lr * DIi,
                                            p_u, 256, BMr, Nn);
            k_mma<40><<<dim3(1, GY, 1), 256>>>(p_u, xpw + lr * 40 * DIi, p_xdbl,
                                               nullptr, DIi, 256, DIi, 0);
            k_scan<<<dim3(BMr, 1), 256>>>(p_xz, 512, p_xdbl, 0, p_u, 256,
                                          dtw + lr * DIi * DTRr, dtbv + lr * DIi,
                                          alog + lr * DIi * NSTn, dssm + lr * DIi,
                                          p_ys, 256, Nn);
            k_mma<128><<<dim3(2, GY, 1), 256>>>(p_ys, outw + lr * Dd * DIi, yT[l + 1],
                                                p_tokin, DIi, DIi, DIi, 2);
        }

        // ---- channel mixing (fwd+bwd fused; transposed epilogue writes yC) ----
        P5 pc = {}, pd = {};
        for (int i = 0; i <= l + 1; ++i) pc.p[i] = yT[i];
        for (int i = 0; i <= l; ++i)     pd.p[i] = yC[i];
        switch (l) {
            case 0: k_combineln<1, 2, 1><<<TT / 4, 128>>>(pc, theta + l * (NLl + 1), pd, gma + l * NLl,
                        cnw + l * Dd, cnb + l * Dd, p_tokin, p_chr); break;
            case 1: k_combineln<1, 3, 2><<<TT / 4, 128>>>(pc, theta + l * (NLl + 1), pd, gma + l * NLl,
                        cnw + l * Dd, cnb + l * Dd, p_tokin, p_chr); break;
            case 2: k_combineln<1, 4, 3><<<TT / 4, 128>>>(pc, theta + l * (NLl + 1), pd, gma + l * NLl,
                        cnw + l * Dd, cnb + l * Dd, p_tokin, p_chr); break;
            default: k_combineln<1, 5, 4><<<TT / 4, 128>>>(pc, theta + l * (NLl + 1), pd, gma + l * NLl,
                        cnw + l * Dd, cnb + l * Dd, p_tokin, p_chr); break;
        }
        {
            size_t lr = (size_t)(l * 3 + 1);       // role 1; role 2 contiguous after
            k_mma<1024><<<dim3(16, GY, 1), 256>>>(p_chr, inw + lr * 2 * DIi * Dd, p_xz,
                                                  nullptr, Dd, Dd, Dd, 0);
            k_conv<<<dim3(CONVG, 2), 256>>>(p_xz, 1024, cvw + lr * DIi * DCc, cvb + lr * DIi,
                                            p_u, 512, BNb, Mm);
            // dual-role x_proj: blockIdx.z selects role (A+=z*256, B+=z*40*K, C+=z*TT*40)
            k_mma<40><<<dim3(1, GY, 2), 256>>>(p_u, xpw + lr * 40 * DIi, p_xdbl,
                                               nullptr, DIi, 512, DIi, 8);
            k_scan<<<dim3(BNb, 2), 256>>>(p_xz, 1024, p_xdbl, (size_t)TT * 40, p_u, 512,
                                          dtw + lr * DIi * DTRr, dtbv + lr * DIi,
                                          alog + lr * DIi * NSTn, dssm + lr * DIi,
                                          p_ys, 512, Mm);
            k_mma<128><<<dim3(2, GY, 1), 256>>>(p_ys, p_wpack + (size_t)l * 65536, yC[l + 1],
                                                p_tokin, 512, 512, 512, 2 | 4);
        }
    }

    k_ln<<<TT / 4, 128>>>(yC[4], n2w1, n2b1, p_tmp, TT);
    k_ln_n<<<(BMr * Dd + 255) / 256, 256>>>(p_tmp, n2w2, n2b2, p_norm);
    k_mma<96><<<dim3(2, 4, KSPLIT), 256>>>(p_norm, headw, p_headp, nullptr,
                                           Nn * Dd, Nn * Dd, 384, 0);
    k_headred<<<(Bb * PREDp * Mm + 255) / 256, 256>>>(p_headp, headb, p_mean, p_std,
                                                      (float*)d_out);
}

// round 17
// speedup vs baseline: 1.0349x; 1.0266x over previous
#include <cuda_runtime.h>
#include <cuda_bf16.h>
#include <math.h>
#include <stdint.h>

// ---- problem dims ----
#define Bb   16
#define Ll   512
#define Mm   32
#define PREDp 96
#define Pp   16
#define Sss  8
#define Dd   128
#define NSTn 16
#define DCc  4
#define NLl  4
#define Nn   63
#define DIi  256
#define DTRr 8
#define BMr  512
#define TT   32256        // = 512*63 = 1008*32 = 252*128
#define BNb  1008
#define KSPLIT 21         // head GEMM split-K slices (8064 = 21*384)

// ---- static device scratch ----
__device__ float g_y[9][(size_t)TT * Dd];
__device__ float g_xn[(size_t)BMr * Ll];
__device__ float g_mean[BMr];
__device__ float g_std[BMr];
__device__ float g_tokin[(size_t)TT * Dd];
__device__ float g_xz[(size_t)TT * 1024];      // up to 2 roles x (xi|z)
__device__ float g_u[(size_t)TT * 512];        // conv+silu output, up to 2 roles
__device__ float g_xdbl[(size_t)TT * 80];      // x_proj output, up to 2 roles x 40
__device__ float g_ys[(size_t)TT * 512];       // scan output, up to 2 roles
__device__ float g_tmp[(size_t)TT * Dd];
__device__ float g_norm[(size_t)TT * Dd];
__device__ float g_chr[(size_t)TT * Dd];
__device__ float g_wpack[4 * 128 * 512];
__device__ float g_headp[(size_t)KSPLIT * BMr * PREDp];

// ======================= warp-mma bf16-split GEMM =======================
// C[M,NT] = A[M,K] @ Bw[NT,K]^T, fp32 in/out, bf16 hi/lo split (3 HMMA terms).
// A row stride = lda (>= K), B row stride = K.
// grid = (ceil(NT/64), M/128, nz), block = 256 (8 warps of 32x32 tiles).
// flags: 1 = accumulate into C, 2 = add R, 4 = transposed epilogue,
//        8 = dual-role mode (blockIdx.z selects role: A+=z*256, B+=z*40*K, C+=z*TT*40).

#define SASTR 40   // smem row stride (bf16): 80B -> conflict-free ldmatrix

__device__ __forceinline__ uint32_t smem_u32(const void* p) {
    return (uint32_t)__cvta_generic_to_shared(p);
}

__device__ __forceinline__ void mma16816(float* d, const uint32_t* a, const uint32_t* b) {
    asm volatile(
        "mma.sync.aligned.m16n8k16.row.col.f32.bf16.bf16.f32 "
        "{%0,%1,%2,%3},{%4,%5,%6,%7},{%8,%9},{%0,%1,%2,%3};"
        : "+f"(d[0]), "+f"(d[1]), "+f"(d[2]), "+f"(d[3])
        : "r"(a[0]), "r"(a[1]), "r"(a[2]), "r"(a[3]), "r"(b[0]), "r"(b[1]));
}

__device__ __forceinline__ void ldm_x4(uint32_t* r, uint32_t a) {
    asm volatile("ldmatrix.sync.aligned.m8n8.x4.shared.b16 {%0,%1,%2,%3}, [%4];"
                 : "=r"(r[0]), "=r"(r[1]), "=r"(r[2]), "=r"(r[3]) : "r"(a));
}

union BH2 { __nv_bfloat16 h[2]; uint32_t u; };

__device__ __forceinline__ int trow(int row) {
    int m = row & 31;
    int bn = row >> 5;
    int n = bn % Nn, b = bn / Nn;
    return (b * Mm + m) * Nn + n;
}

template <int NT>
__global__ __launch_bounds__(256) void k_mma(const float* __restrict__ A,
                                             const float* __restrict__ Bw,
                                             float* __restrict__ C,
                                             const float* __restrict__ R,
                                             int K, int lda, int klen, int flags) {
    __shared__ __nv_bfloat16 sA[2][128 * SASTR];
    __shared__ __nv_bfloat16 sB[2][64 * SASTR];

    int tid = threadIdx.x;
    int warp = tid >> 5, lane = tid & 31;
    int gq = lane >> 2, tig = lane & 3;
    int warpM = warp >> 1, warpN = warp & 1;
    int m0 = blockIdx.y * 128;
    int n0 = blockIdx.x * 64;
    int kbeg;
    if (flags & 8) {
        A  += (size_t)blockIdx.z * 256;
        Bw += (size_t)blockIdx.z * 40 * K;
        C  += (size_t)blockIdx.z * ((size_t)TT * 40);
        kbeg = 0;
    } else {
        kbeg = blockIdx.z * klen;
        C += (size_t)blockIdx.z * ((size_t)gridDim.y * 128) * NT;
    }

    int g = lane >> 3, rr = lane & 7;
    int aoff = (warpM * 32 + (g & 1) * 8 + rr) * SASTR + (g >> 1) * 8;
    int boff = (warpN * 32 + (g >> 1) * 8 + rr) * SASTR + (g & 1) * 8;
    uint32_t sA0 = smem_u32(&sA[0][0]), sA1 = smem_u32(&sA[1][0]);
    uint32_t sB0 = smem_u32(&sB[0][0]), sB1 = smem_u32(&sB[1][0]);

    float acc[2][4][4];
#pragma unroll
    for (int i = 0; i < 2; ++i)
#pragma unroll
        for (int j = 0; j < 4; ++j)
#pragma unroll
            for (int r = 0; r < 4; ++r) acc[i][j][r] = 0.f;

    float4 ra[4], rb[2];

    auto ldA = [&](int k0) {
#pragma unroll
        for (int t = 0; t < 4; ++t) {
            int gg = tid + t * 256;
            int row = gg >> 3, c = (gg & 7) << 2;
            ra[t] = *reinterpret_cast<const float4*>(A + (size_t)(m0 + row) * lda + k0 + c);
        }
    };
    auto ldB = [&](int k0) {
#pragma unroll
        for (int t = 0; t < 2; ++t) {
            int gg = tid + t * 256;
            int row = gg >> 3, c = (gg & 7) << 2;
            int grow = n0 + row;
            if ((NT & 63) == 0 || grow < NT)
                rb[t] = *reinterpret_cast<const float4*>(Bw + (size_t)grow * K + k0 + c);
            else
                rb[t] = make_float4(0.f, 0.f, 0.f, 0.f);
        }
    };

    ldA(kbeg); ldB(kbeg);
    int nch = klen >> 5;
    for (int ch = 0; ch < nch; ++ch) {
#pragma unroll
        for (int t = 0; t < 4; ++t) {
            int gg = tid + t * 256;
            int row = gg >> 3, c = (gg & 7) << 2;
            float v[4] = {ra[t].x, ra[t].y, ra[t].z, ra[t].w};
            BH2 h0, h1, l0, l1;
#pragma unroll
            for (int q = 0; q < 2; ++q) {
                h0.h[q] = __float2bfloat16(v[q]);
                l0.h[q] = __float2bfloat16(v[q] - __bfloat162float(h0.h[q]));
                h1.h[q] = __float2bfloat16(v[2 + q]);
                l1.h[q] = __float2bfloat16(v[2 + q] - __bfloat162float(h1.h[q]));
            }
            uint32_t* ph = reinterpret_cast<uint32_t*>(&sA[0][row * SASTR + c]);
            uint32_t* pl = reinterpret_cast<uint32_t*>(&sA[1][row * SASTR + c]);
            ph[0] = h0.u; ph[1] = h1.u; pl[0] = l0.u; pl[1] = l1.u;
        }
#pragma unroll
        for (int t = 0; t < 2; ++t) {
            int gg = tid + t * 256;
            int row = gg >> 3, c = (gg & 7) << 2;
            float v[4] = {rb[t].x, rb[t].y, rb[t].z, rb[t].w};
            BH2 h0, h1, l0, l1;
#pragma unroll
            for (int q = 0; q < 2; ++q) {
                h0.h[q] = __float2bfloat16(v[q]);
                l0.h[q] = __float2bfloat16(v[q] - __bfloat162float(h0.h[q]));
                h1.h[q] = __float2bfloat16(v[2 + q]);
                l1.h[q] = __float2bfloat16(v[2 + q] - __bfloat162float(h1.h[q]));
            }
            uint32_t* ph = reinterpret_cast<uint32_t*>(&sB[0][row * SASTR + c]);
            uint32_t* pl = reinterpret_cast<uint32_t*>(&sB[1][row * SASTR + c]);
            ph[0] = h0.u; ph[1] = h1.u; pl[0] = l0.u; pl[1] = l1.u;
        }
        __syncthreads();
        if (ch + 1 < nch) { ldA(kbeg + ((ch + 1) << 5)); ldB(kbeg + ((ch + 1) << 5)); }

#pragma unroll
        for (int kk = 0; kk < 2; ++kk) {
            int kb = kk * 16;
            uint32_t ah[2][4], al[2][4];
            ldm_x4(ah[0], sA0 + (uint32_t)(aoff + kb) * 2);
            ldm_x4(ah[1], sA0 + (uint32_t)(aoff + 16 * SASTR + kb) * 2);
            ldm_x4(al[0], sA1 + (uint32_t)(aoff + kb) * 2);
            ldm_x4(al[1], sA1 + (uint32_t)(aoff + 16 * SASTR + kb) * 2);
            uint32_t bh[4][2], bl[4][2], t0[4], t1[4];
            ldm_x4(t0, sB0 + (uint32_t)(boff + kb) * 2);
            ldm_x4(t1, sB0 + (uint32_t)(boff + 16 * SASTR + kb) * 2);
            bh[0][0] = t0[0]; bh[0][1] = t0[1]; bh[1][0] = t0[2]; bh[1][1] = t0[3];
            bh[2][0] = t1[0]; bh[2][1] = t1[1]; bh[3][0] = t1[2]; bh[3][1] = t1[3];
            ldm_x4(t0, sB1 + (uint32_t)(boff + kb) * 2);
            ldm_x4(t1, sB1 + (uint32_t)(boff + 16 * SASTR + kb) * 2);
            bl[0][0] = t0[0]; bl[0][1] = t0[1]; bl[1][0] = t0[2]; bl[1][1] = t0[3];
            bl[2][0] = t1[0]; bl[2][1] = t1[1]; bl[3][0] = t1[2]; bl[3][1] = t1[3];
#pragma unroll
            for (int i = 0; i < 2; ++i)
#pragma unroll
                for (int j = 0; j < 4; ++j) {
                    mma16816(acc[i][j], ah[i], bh[j]);
                    mma16816(acc[i][j], ah[i], bl[j]);
                    mma16816(acc[i][j], al[i], bh[j]);
                }
        }
        __syncthreads();
    }

#pragma unroll
    for (int i = 0; i < 2; ++i) {
        int grow = m0 + warpM * 32 + i * 16 + gq;
        int orow0 = (flags & 4) ? trow(grow) : grow;
        int orow1 = (flags & 4) ? trow(grow + 8) : (grow + 8);
#pragma unroll
        for (int j = 0; j < 4; ++j) {
            int gcol = n0 + warpN * 32 + j * 8 + 2 * tig;
            if ((NT & 63) != 0 && gcol >= NT) continue;
            size_t o0 = (size_t)orow0 * NT + gcol;
            size_t o1 = (size_t)orow1 * NT + gcol;
            float2 v0 = make_float2(acc[i][j][0], acc[i][j][1]);
            float2 v1 = make_float2(acc[i][j][2], acc[i][j][3]);
            if (flags & 2) {
                float2 t0 = *reinterpret_cast<const float2*>(R + o0);
                float2 t1 = *reinterpret_cast<const float2*>(R + o1);
                v0.x += t0.x; v0.y += t0.y; v1.x += t1.x; v1.y += t1.y;
            }
            if (flags & 1) {
                float2 t0 = *reinterpret_cast<const float2*>(C + o0);
                float2 t1 = *reinterpret_cast<const float2*>(C + o1);
                v0.x += t0.x; v0.y += t0.y; v1.x += t1.x; v1.y += t1.y;
            }
            *reinterpret_cast<float2*>(C + o0) = v0;
            *reinterpret_cast<float2*>(C + o1) = v1;
        }
    }
}

// ======================= conv + SiLU (elementwise, multi-role) =======================
__global__ void k_conv(const float* __restrict__ xz, int xzs,
                       const float* __restrict__ cw, const float* __restrict__ cb,
                       float* __restrict__ u, int ustr, int batch, int slen) {
    int r = blockIdx.y;
    int rev = r;
    xz += (size_t)r * 512;
    cw += (size_t)r * DIi * DCc;
    cb += (size_t)r * DIi;
    u  += (size_t)r * 256;
    int idx = blockIdx.x * 256 + threadIdx.x;
    int total = batch * slen * DIi;
    if (idx >= total) return;
    int c = idx & 255;
    int row = idx >> 8;
    int s = row % slen, b = row / slen;
    float acc = cb[c];
#pragma unroll
    for (int k = 0; k < DCc; ++k) {
        int t = rev ? (s + 3 - k) : (s + k - 3);
        if (t >= 0 && t < slen)
            acc = fmaf(cw[c * DCc + k], xz[((size_t)(b * slen + t)) * xzs + c], acc);
    }
    u[(size_t)row * ustr + c] = acc / (1.f + __expf(-acc));
}

// ======================= scan (per-warp xd staging, syncwarp only) =======================
__global__ __launch_bounds__(256) void k_scan(
    const float* __restrict__ xz, int xzs,
    const float* __restrict__ xdbl, size_t xdstr,
    const float* __restrict__ u, int ustr,
    const float* __restrict__ dtw, const float* __restrict__ dtb,
    const float* __restrict__ alog, const float* __restrict__ dssm,
    float* __restrict__ y, int ystr, int slen) {
    __shared__ float sxd[8][40];       // per-warp private staging

    int r = blockIdx.y;
    int rev = r;
    xz   += (size_t)r * 512;
    xdbl += (size_t)r * xdstr;
    u    += (size_t)r * 256;
    dtw  += (size_t)r * DIi * DTRr;
    dtb  += (size_t)r * DIi;
    alog += (size_t)r * DIi * NSTn;
    dssm += (size_t)r * DIi;
    y    += (size_t)r * 256;

    int c = threadIdx.x;
    int wid = c >> 5, lane = c & 31;
    int b = blockIdx.x;

    float dtwr[DTRr];
#pragma unroll
    for (int q = 0; q < DTRr; ++q) dtwr[q] = dtw[c * DTRr + q];
    float dtbr = dtb[c];
    float dss = dssm[c];

    float a[NSTn];
#pragma unroll
    for (int n = 0; n < NSTn; ++n) a[n] = -__expf(alog[c * NSTn + n]);
    float a0 = a[0];
    bool geom = true;
#pragma unroll
    for (int n = 1; n < NSTn; ++n)
        geom = geom && (fabsf(a[n] - (float)(n + 1) * a0) <= 1e-4f * fabsf(a[n]));
    float h[NSTn];
#pragma unroll
    for (int n = 0; n < NSTn; ++n) h[n] = 0.f;

    size_t base = (size_t)b * slen;
    int s0 = rev ? slen - 1 : 0;
    float uv_nx = u[(base + s0) * ustr + c];
    float z_nx  = xz[(base + s0) * xzs + DIi + c];
    float2 xdp = make_float2(0.f, 0.f);            // per-warp prefetch (lanes 0..19)
    if (lane < 20)
        xdp = *reinterpret_cast<const float2*>(xdbl + (base + s0) * 40 + lane * 2);

    for (int step = 0; step < slen; ++step) {
        int s = rev ? slen - 1 - step : step;
        if (lane < 20) {
            sxd[wid][lane * 2]     = xdp.x;
            sxd[wid][lane * 2 + 1] = xdp.y;
        }
        float uv = uv_nx, zv = z_nx;
        __syncwarp();
        if (step + 1 < slen) {
            int sn = rev ? s - 1 : s + 1;
            if (lane < 20)
                xdp = *reinterpret_cast<const float2*>(xdbl + (base + sn) * 40 + lane * 2);
            uv_nx = u[(base + sn) * ustr + c];
            z_nx  = xz[(base + sn) * xzs + DIi + c];
        }
        const float* xd = sxd[wid];
        float dtacc = dtbr;
#pragma unroll
        for (int q = 0; q < DTRr; ++q) dtacc = fmaf(xd[q], dtwr[q], dtacc);
        float dtv = (dtacc > 20.f) ? dtacc : __logf(1.f + __expf(dtacc));
        float du = dtv * uv;
        float ysum = 0.f;
        if (geom) {
            float w = __expf(dtv * a0);
            float e = 1.f;
#pragma unroll
            for (int n = 0; n < NSTn; ++n) {
                e *= w;
                h[n] = fmaf(h[n], e, du * xd[8 + n]);
                ysum = fmaf(h[n], xd[24 + n], ysum);
            }
        } else {
#pragma unroll
            for (int n = 0; n < NSTn; ++n) {
                float e = __expf(dtv * a[n]);
                h[n] = fmaf(h[n], e, du * xd[8 + n]);
                ysum = fmaf(h[n], xd[24 + n], ysum);
            }
        }
        float sg = 1.f / (1.f + __expf(-zv));
        y[(base + s) * ystr + c] = (ysum + uv * dss) * (zv * sg);
        __syncwarp();   // reads done before next step's overwrite
    }
}

// ======================= fused combine + LN (+transpose), float4 ==========
struct P5 { const float* p[5]; };

template <int TRANS, int NA, int NB>
__global__ void k_combineln(P5 pa, const float* __restrict__ ra,
                            P5 pb, const float* __restrict__ rb,
                            const float* __restrict__ w, const float* __restrict__ bia,
                            float* __restrict__ comb, float* __restrict__ normout) {
    __shared__ float ca[5], cb2[5];
    if (threadIdx.x == 0) {
        float mx = -1e30f;
#pragma unroll
        for (int i = 0; i < NA; ++i) mx = fmaxf(mx, ra[i]);
        float s = 0.f;
#pragma unroll
        for (int i = 0; i < NA; ++i) { ca[i] = __expf(ra[i] - mx); s += ca[i]; }
#pragma unroll
        for (int i = 0; i < NA; ++i) ca[i] /= s;
        mx = -1e30f;
#pragma unroll
        for (int i = 0; i < NB; ++i) mx = fmaxf(mx, rb[i]);
        s = 0.f;
#pragma unroll
        for (int i = 0; i < NB; ++i) { cb2[i] = __expf(rb[i] - mx); s += cb2[i]; }
#pragma unroll
        for (int i = 0; i < NB; ++i) cb2[i] /= s;
    }
    __syncthreads();
    int warp = threadIdx.x >> 5, lane = threadIdx.x & 31;
    int row = blockIdx.x * 4 + warp;
    if (row >= TT) return;
    int irow = row;
    if (TRANS) {
        int m = row & 31;
        int bn = row >> 5;
        int n = bn % Nn, b = bn / Nn;
        irow = (b * Mm + m) * Nn + n;
    }
    float wa[5], wb[5];
#pragma unroll
    for (int j = 0; j < NA; ++j) wa[j] = ca[j];
#pragma unroll
    for (int j = 0; j < NB; ++j) wb[j] = cb2[j];

    size_t ibase = (size_t)irow * Dd + lane * 4;
    float v[4] = {0.f, 0.f, 0.f, 0.f};
#pragma unroll
    for (int j = 0; j < NA; ++j) {
        float4 t = *reinterpret_cast<const float4*>(pa.p[j] + ibase);
        v[0] = fmaf(wa[j], t.x, v[0]); v[1] = fmaf(wa[j], t.y, v[1]);
        v[2] = fmaf(wa[j], t.z, v[2]); v[3] = fmaf(wa[j], t.w, v[3]);
    }
#pragma unroll
    for (int j = 0; j < NB; ++j) {
        float4 t = *reinterpret_cast<const float4*>(pb.p[j] + ibase);
        v[0] = fmaf(wb[j], t.x, v[0]); v[1] = fmaf(wb[j], t.y, v[1]);
        v[2] = fmaf(wb[j], t.z, v[2]); v[3] = fmaf(wb[j], t.w, v[3]);
    }
    *reinterpret_cast<float4*>(comb + ibase) = make_float4(v[0], v[1], v[2], v[3]);

    float s = v[0] + v[1] + v[2] + v[3];
#pragma unroll
    for (int o = 16; o; o >>= 1) s += __shfl_xor_sync(0xffffffffu, s, o);
    float mu = s * (1.f / Dd);
    float q0 = 0.f;
#pragma unroll
    for (int q = 0; q < 4; ++q) { v[q] -= mu; q0 += v[q] * v[q]; }
#pragma unroll
    for (int o = 16; o; o >>= 1) q0 += __shfl_xor_sync(0xffffffffu, q0, o);
    float r = rsqrtf(q0 * (1.f / Dd) + 1e-5f);
    float4 wv = *reinterpret_cast<const float4*>(w + lane * 4);
    float4 bv = *reinterpret_cast<const float4*>(bia + lane * 4);
    float4 ov;
    ov.x = v[0] * r * wv.x + bv.x;
    ov.y = v[1] * r * wv.y + bv.y;
    ov.z = v[2] * r * wv.z + bv.z;
    ov.w = v[3] * r * wv.w + bv.w;
    *reinterpret_cast<float4*>(normout + (size_t)row * Dd + lane * 4) = ov;
}

// ======================= other supporting kernels =======================

__global__ void k_stats(const float* __restrict__ x, float* __restrict__ mean,
                        float* __restrict__ stdv, float* __restrict__ xn) {
    int bm = blockIdx.x;
    int b = bm >> 5, m = bm & 31;
    int tid = threadIdx.x;
    float s = 0.f, sq = 0.f;
    for (int l = tid; l < Ll; l += 256) {
        float v = x[((size_t)b * Ll + l) * Mm + m];
        s += v; sq += v * v;
    }
    __shared__ float sh1[256], sh2[256];
    sh1[tid] = s; sh2[tid] = sq;
    __syncthreads();
    for (int o = 128; o; o >>= 1) {
        if (tid < o) { sh1[tid] += sh1[tid + o]; sh2[tid] += sh2[tid + o]; }
        __syncthreads();
    }
    __shared__ float smu, ssd;
    if (tid == 0) {
        float mu = sh1[0] / (float)Ll;
        float var = (sh2[0] - (float)Ll * mu * mu) / (float)(Ll - 1);
        if (var < 0.f) var = 0.f;
        float sd = sqrtf(var) + 1e-5f;
        smu = mu; ssd = sd;
        mean[bm] = mu; stdv[bm] = sd;
    }
    __syncthreads();
    float inv = 1.f / ssd;
    float mu = smu;
    for (int l = tid; l < Ll; l += 256) {
        xn[(size_t)bm * Ll + l] = (x[((size_t)b * Ll + l) * Mm + m] - mu) * inv;
    }
}

__global__ void k_patch(const float* __restrict__ xn, const float* __restrict__ pw,
                        const float* __restrict__ pb, const float* __restrict__ pos,
                        float* __restrict__ h) {
    int blk = blockIdx.x;
    int n = blk % Nn, bm = blk / Nn;
    int d = threadIdx.x;
    __shared__ float xs[Pp];
    if (d < Pp) xs[d] = xn[(size_t)bm * Ll + n * Sss + d];
    __syncthreads();
    float acc = pb[d];
#pragma unroll
    for (int p = 0; p < Pp; ++p) acc = fmaf(xs[p], pw[d * Pp + p], acc);
    acc += pos[n * Dd + d];
    h[(size_t)blk * Dd + d] = acc;
}

__global__ void k_ln(const float* __restrict__ x, const float* __restrict__ w,
                     const float* __restrict__ bia, float* __restrict__ out, int rows) {
    int warp = threadIdx.x >> 5, lane = threadIdx.x & 31;
    int row = blockIdx.x * 4 + warp;
    if (row >= rows) return;
    const float* xr = x + (size_t)row * Dd;
    float v0 = xr[lane], v1 = xr[lane + 32], v2 = xr[lane + 64], v3 = xr[lane + 96];
    float s = v0 + v1 + v2 + v3;
#pragma unroll
    for (int o = 16; o; o >>= 1) s += __shfl_xor_sync(0xffffffffu, s, o);
    float mu = s * (1.f / Dd);
    float d0 = v0 - mu, d1 = v1 - mu, d2 = v2 - mu, d3 = v3 - mu;
    float q = d0 * d0 + d1 * d1 + d2 * d2 + d3 * d3;
#pragma unroll
    for (int o = 16; o; o >>= 1) q += __shfl_xor_sync(0xffffffffu, q, o);
    float r = rsqrtf(q * (1.f / Dd) + 1e-5f);
    float* orow = out + (size_t)row * Dd;
    orow[lane]      = d0 * r * w[lane]      + bia[lane];
    orow[lane + 32] = d1 * r * w[lane + 32] + bia[lane + 32];
    orow[lane + 64] = d2 * r * w[lane + 64] + bia[lane + 64];
    orow[lane + 96] = d3 * r * w[lane + 96] + bia[lane + 96];
}

__global__ void k_ln_n(const float* __restrict__ x, const float* __restrict__ w2,
                       const float* __restrict__ b2, float* __restrict__ out) {
    int idx = blockIdx.x * 256 + threadIdx.x;
    if (idx >= BMr * Dd) return;
    int d = idx & 127, bm = idx >> 7;
    const float* base = x + (size_t)bm * Nn * Dd + d;
    float s = 0.f, q = 0.f;
    for (int n = 0; n < Nn; ++n) { float v = base[(size_t)n * Dd]; s += v; q += v * v; }
    float mu = s * (1.f / Nn);
    float var = q * (1.f / Nn) - mu * mu;
    if (var < 0.f) var = 0.f;
    float r = rsqrtf(var + 1e-5f);
    float* ob = out + (size_t)bm * Nn * Dd + d;
    for (int n = 0; n < Nn; ++n)
        ob[(size_t)n * Dd] = (base[(size_t)n * Dd] - mu) * r * w2[n] + b2[n];
}

__global__ void k_repack_all(const float* __restrict__ outw, float* __restrict__ wp) {
    int idx = blockIdx.x * 256 + threadIdx.x;
    if (idx >= 4 * 128 * 256) return;
    int lyr = idx >> 15, rem = idx & 32767;
    int d = rem >> 8, k = rem & 255;
    size_t o = (size_t)lyr * 65536 + d * 512 + k;
    wp[o]       = outw[(size_t)(lyr * 3 + 1) * 32768 + d * 256 + k];
    wp[o + 256] = outw[(size_t)(lyr * 3 + 2) * 32768 + d * 256 + k];
}

__global__ void k_headred(const float* __restrict__ hp, const float* __restrict__ hb,
                          const float* __restrict__ mean, const float* __restrict__ stdv,
                          float* __restrict__ out) {
    int idx = blockIdx.x * 256 + threadIdx.x;
    if (idx >= Bb * PREDp * Mm) return;
    int m = idx % Mm;
    int p = (idx / Mm) % PREDp;
    int b = idx / (Mm * PREDp);
    int bm = b * Mm + m;
    float s = 0.f;
#pragma unroll 3
    for (int z = 0; z < KSPLIT; ++z)
        s += hp[(size_t)z * BMr * PREDp + (size_t)bm * PREDp + p];
    out[idx] = (s + hb[p]) * stdv[bm] + mean[bm];
}

// ======================= host orchestration =======================

extern "C" void kernel_launch(void* const* d_in, const int* in_sizes, int n_in,
                              void* d_out, int out_size) {
    (void)in_sizes; (void)n_in; (void)out_size;
    const float* x      = (const float*)d_in[0];
    const float* patchw = (const float*)d_in[1];
    const float* patchb = (const float*)d_in[2];
    const float* pos    = (const float*)d_in[3];
    const float* alpha  = (const float*)d_in[4];
    const float* beta   = (const float*)d_in[5];
    const float* theta  = (const float*)d_in[6];
    const float* gma    = (const float*)d_in[7];
    const float* tnw    = (const float*)d_in[8];
    const float* tnb    = (const float*)d_in[9];
    const float* cnw    = (const float*)d_in[10];
    const float* cnb    = (const float*)d_in[11];
    const float* inw    = (const float*)d_in[12];
    const float* cvw    = (const float*)d_in[13];
    const float* cvb    = (const float*)d_in[14];
    const float* xpw    = (const float*)d_in[15];
    const float* dtw    = (const float*)d_in[16];
    const float* dtbv   = (const float*)d_in[17];
    const float* alog   = (const float*)d_in[18];
    const float* dssm   = (const float*)d_in[19];
    const float* outw   = (const float*)d_in[20];
    const float* n2w1   = (const float*)d_in[21];
    const float* n2b1   = (const float*)d_in[22];
    const float* n2w2   = (const float*)d_in[23];
    const float* n2b2   = (const float*)d_in[24];
    const float* headw  = (const float*)d_in[25];
    const float* headb  = (const float*)d_in[26];

    float *p_y, *p_xn, *p_mean, *p_std, *p_tokin, *p_norm, *p_chr;
    float *p_xz, *p_u, *p_xdbl, *p_ys, *p_tmp, *p_headp, *p_wpack;
    cudaGetSymbolAddress((void**)&p_y,     g_y);
    cudaGetSymbolAddress((void**)&p_xn,    g_xn);
    cudaGetSymbolAddress((void**)&p_mean,  g_mean);
    cudaGetSymbolAddress((void**)&p_std,   g_std);
    cudaGetSymbolAddress((void**)&p_tokin, g_tokin);
    cudaGetSymbolAddress((void**)&p_norm,  g_norm);
    cudaGetSymbolAddress((void**)&p_chr,   g_chr);
    cudaGetSymbolAddress((void**)&p_xz,    g_xz);
    cudaGetSymbolAddress((void**)&p_u,     g_u);
    cudaGetSymbolAddress((void**)&p_xdbl,  g_xdbl);
    cudaGetSymbolAddress((void**)&p_ys,    g_ys);
    cudaGetSymbolAddress((void**)&p_tmp,   g_tmp);
    cudaGetSymbolAddress((void**)&p_headp, g_headp);
    cudaGetSymbolAddress((void**)&p_wpack, g_wpack);

    float* yT[5]; float* yC[5];
    yT[0] = p_y; yC[0] = p_y;
    for (int i = 1; i <= 4; ++i) {
        yT[i] = p_y + (size_t)i * TT * Dd;
        yC[i] = p_y + (size_t)(4 + i) * TT * Dd;
    }

    k_repack_all<<<512, 256>>>(outw, p_wpack);
    k_stats<<<BMr, 256>>>(x, p_mean, p_std, p_xn);
    k_patch<<<TT, Dd>>>(p_xn, patchw, patchb, pos, p_y);

    const int GY = TT / 128;        // 252
    const int CONVG = (TT * DIi + 255) / 256;

    for (int l = 0; l < NLl; ++l) {
        // ---- token mixing ----
        P5 pa = {}, pb = {};
        for (int i = 0; i <= l; ++i) { pa.p[i] = yT[i]; pb.p[i] = yC[i]; }
        switch (l) {
            case 0: k_combineln<0, 1, 1><<<TT / 4, 128>>>(pa, alpha + l * NLl, pb, beta + l * NLl,
                        tnw + l * Dd, tnb + l * Dd, p_tokin, p_norm); break;
            case 1: k_combineln<0, 2, 2><<<TT / 4, 128>>>(pa, alpha + l * NLl, pb, beta + l * NLl,
                        tnw + l * Dd, tnb + l * Dd, p_tokin, p_norm); break;
            case 2: k_combineln<0, 3, 3><<<TT / 4, 128>>>(pa, alpha + l * NLl, pb, beta + l * NLl,
                        tnw + l * Dd, tnb + l * Dd, p_tokin, p_norm); break;
            default: k_combineln<0, 4, 4><<<TT / 4, 128>>>(pa, alpha + l * NLl, pb, beta + l * NLl,
                        tnw + l * Dd, tnb + l * Dd, p_tokin, p_norm); break;
        }
        {
            size_t lr = (size_t)(l * 3 + 0);
            k_mma<512><<<dim3(8, GY, 1), 256>>>(p_norm, inw + lr * 2 * DIi * Dd, p_xz,
                                                nullptr, Dd, Dd, Dd, 0);
            k_conv<<<dim3(CONVG, 1), 256>>>(p_xz, 512, cvw + lr * DIi * DCc, cvb + lr * DIi,
                                            p_u, 256, BMr, Nn);
            k_mma<40><<<dim3(1, GY, 1), 256>>>(p_u, xpw + lr * 40 * DIi, p_xdbl,
                                               nullptr, DIi, 256, DIi, 0);
            k_scan<<<dim3(BMr, 1), 256>>>(p_xz, 512, p_xdbl, 0, p_u, 256,
                                          dtw + lr * DIi * DTRr, dtbv + lr * DIi,
                                          alog + lr * DIi * NSTn, dssm + lr * DIi,
                                          p_ys, 256, Nn);
            k_mma<128><<<dim3(2, GY, 1), 256>>>(p_ys, outw + lr * Dd * DIi, yT[l + 1],
                                                p_tokin, DIi, DIi, DIi, 2);
        }

        // ---- channel mixing (fwd+bwd fused; transposed epilogue writes yC) ----
        P5 pc = {}, pd = {};
        for (int i = 0; i <= l + 1; ++i) pc.p[i] = yT[i];
        for (int i = 0; i <= l; ++i)     pd.p[i] = yC[i];
        switch (l) {
            case 0: k_combineln<1, 2, 1><<<TT / 4, 128>>>(pc, theta + l * (NLl + 1), pd, gma + l * NLl,
                        cnw + l * Dd, cnb + l * Dd, p_tokin, p_chr); break;
            case 1: k_combineln<1, 3, 2><<<TT / 4, 128>>>(pc, theta + l * (NLl + 1), pd, gma + l * NLl,
                        cnw + l * Dd, cnb + l * Dd, p_tokin, p_chr); break;
            case 2: k_combineln<1, 4, 3><<<TT / 4, 128>>>(pc, theta + l * (NLl + 1), pd, gma + l * NLl,
                        cnw + l * Dd, cnb + l * Dd, p_tokin, p_chr); break;
            default: k_combineln<1, 5, 4><<<TT / 4, 128>>>(pc, theta + l * (NLl + 1), pd, gma + l * NLl,
                        cnw + l * Dd, cnb + l * Dd, p_tokin, p_chr); break;
        }
        {
            size_t lr = (size_t)(l * 3 + 1);       // role 1; role 2 contiguous after
            k_mma<1024><<<dim3(16, GY, 1), 256>>>(p_chr, inw + lr * 2 * DIi * Dd, p_xz,
                                                  nullptr, Dd, Dd, Dd, 0);
            k_conv<<<dim3(CONVG, 2), 256>>>(p_xz, 1024, cvw + lr * DIi * DCc, cvb + lr * DIi,
                                            p_u, 512, BNb, Mm);
            // dual-role x_proj: blockIdx.z selects role (A+=z*256, B+=z*40*K, C+=z*TT*40)
            k_mma<40><<<dim3(1, GY, 2), 256>>>(p_u, xpw + lr * 40 * DIi, p_xdbl,
                                               nullptr, DIi, 512, DIi, 8);
            k_scan<<<dim3(BNb, 2), 256>>>(p_xz, 1024, p_xdbl, (size_t)TT * 40, p_u, 512,
                                          dtw + lr * DIi * DTRr, dtbv + lr * DIi,
                                          alog + lr * DIi * NSTn, dssm + lr * DIi,
                                          p_ys, 512, Mm);
            k_mma<128><<<dim3(2, GY, 1), 256>>>(p_ys, p_wpack + (size_t)l * 65536, yC[l + 1],
                                                p_tokin, 512, 512, 512, 2 | 4);
        }
    }

    k_ln<<<TT / 4, 128>>>(yC[4], n2w1, n2b1, p_tmp, TT);
    k_ln_n<<<(BMr * Dd + 255) / 256, 256>>>(p_tmp, n2w2, n2b2, p_norm);
    k_mma<96><<<dim3(2, 4, KSPLIT), 256>>>(p_norm, headw, p_headp, nullptr,
                                           Nn * Dd, Nn * Dd, 384, 0);
    k_headred<<<(Bb * PREDp * Mm + 255) / 256, 256>>>(p_headp, headb, p_mean, p_std,
                                                      (float*)d_out);
}